// round 2
// baseline (speedup 1.0000x reference)
#include <cuda_runtime.h>
#include <math.h>

// Problem constants
#define Bq    4
#define Lq    4096
#define Dq    1024
#define Hq    16
#define DHq   64
#define MTOK  (Bq*Lq)      // 16384
#define NQKV  (3*Dq)       // 3072
#define RMSEPS 1.1920929e-07f
#define EPSLIN 1e-06f

// Scratch (device globals — no allocation allowed)
__device__ float g_qkv [(size_t)MTOK * NQKV];   // 201 MB, qkv then in-place qf/kf
__device__ float g_vkp [16 * 64 * 65 * DHq];    // split-L partials (deterministic)
__device__ float g_vk  [64 * 65 * DHq];         // reduced vk per (b,h)
__device__ float g_attn[(size_t)MTOK * Dq];     // merged-head attention output
__device__ float g_y   [(size_t)MTOK * Dq];     // out GEMM result pre-rmsnorm
__device__ float g_cos [Lq * 32];
__device__ float g_sin [Lq * 32];

// ---------------------------------------------------------------------------
// K0: RoPE tables. Mimic reference fp32 rounding: ang = fl(l * inv_freq_f32).
// ---------------------------------------------------------------------------
__global__ void rope_tables_k() {
    int idx = blockIdx.x * blockDim.x + threadIdx.x;
    if (idx >= Lq * 32) return;
    int l = idx >> 5, j = idx & 31;
    // inv_freq[j] = 10000^(-j/32)
    float inv_freq = expf(-(float)j * (9.210340371976184f / 32.0f));
    float ang = (float)l * inv_freq;
    g_cos[idx] = cosf(ang);
    g_sin[idx] = sinf(ang);
}

// ---------------------------------------------------------------------------
// K1/K6: C[m,n] = sum_k A[m,k]*W[n,k] + bias[n]   (both operands K-major)
// 128x128x8 tile, 256 threads, 8x8 per thread.
// ---------------------------------------------------------------------------
__global__ __launch_bounds__(256, 2) void gemm_tn_k(
    const float* __restrict__ A, const float* __restrict__ W,
    const float* __restrict__ bias, float* __restrict__ C,
    int N, int K)
{
    __shared__ __align__(16) float As[8][128];
    __shared__ __align__(16) float Bs[8][128];
    const int tid = threadIdx.x;
    const int m0 = blockIdx.y * 128;
    const int n0 = blockIdx.x * 128;
    const int lr = tid >> 1;
    const int lc = (tid & 1) << 2;
    const float* Ap = A + (size_t)(m0 + lr) * K + lc;
    const float* Wp = W + (size_t)(n0 + lr) * K + lc;
    const int tx = (tid & 15) << 3;
    const int ty = (tid >> 4) << 3;
    float acc[8][8];
#pragma unroll
    for (int i = 0; i < 8; ++i)
#pragma unroll
        for (int j = 0; j < 8; ++j) acc[i][j] = 0.0f;

    for (int kt = 0; kt < K; kt += 8) {
        float4 av = *(const float4*)(Ap + kt);
        float4 wv = *(const float4*)(Wp + kt);
        As[lc+0][lr] = av.x; As[lc+1][lr] = av.y; As[lc+2][lr] = av.z; As[lc+3][lr] = av.w;
        Bs[lc+0][lr] = wv.x; Bs[lc+1][lr] = wv.y; Bs[lc+2][lr] = wv.z; Bs[lc+3][lr] = wv.w;
        __syncthreads();
#pragma unroll
        for (int k = 0; k < 8; ++k) {
            float a[8], b[8];
            *(float4*)(a)     = *(const float4*)&As[k][ty];
            *(float4*)(a + 4) = *(const float4*)&As[k][ty + 4];
            *(float4*)(b)     = *(const float4*)&Bs[k][tx];
            *(float4*)(b + 4) = *(const float4*)&Bs[k][tx + 4];
#pragma unroll
            for (int i = 0; i < 8; ++i)
#pragma unroll
                for (int j = 0; j < 8; ++j)
                    acc[i][j] = fmaf(a[i], b[j], acc[i][j]);
        }
        __syncthreads();
    }
#pragma unroll
    for (int i = 0; i < 8; ++i) {
        const int m = m0 + ty + i;
        float* Crow = C + (size_t)m * N + n0 + tx;
#pragma unroll
        for (int j = 0; j < 8; j += 4) {
            float4 o;
            o.x = acc[i][j+0] + bias[n0 + tx + j + 0];
            o.y = acc[i][j+1] + bias[n0 + tx + j + 1];
            o.z = acc[i][j+2] + bias[n0 + tx + j + 2];
            o.w = acc[i][j+3] + bias[n0 + tx + j + 3];
            *(float4*)(Crow + j) = o;
        }
    }
}

// ---------------------------------------------------------------------------
// K2: per-token rmsnorm(q), rmsnorm(k), RoPE, ReLU — in place in g_qkv.
// One CTA (256 thr) per token, 4 elements/thread (one full RoPE pair x2).
// ---------------------------------------------------------------------------
__global__ __launch_bounds__(256) void qk_prep_k(const float* __restrict__ gq,
                                                 const float* __restrict__ gk)
{
    const int t = blockIdx.x;
    const int l = t & (Lq - 1);
    const int tid = threadIdx.x;
    float* row = g_qkv + (size_t)t * NQKV;
    float4 q = *(float4*)(row + tid * 4);
    float4 k = *(float4*)(row + Dq + tid * 4);
    float sq = q.x*q.x + q.y*q.y + q.z*q.z + q.w*q.w;
    float sk = k.x*k.x + k.y*k.y + k.z*k.z + k.w*k.w;
#pragma unroll
    for (int o = 16; o > 0; o >>= 1) {
        sq += __shfl_xor_sync(0xffffffffu, sq, o);
        sk += __shfl_xor_sync(0xffffffffu, sk, o);
    }
    __shared__ float wq[8], wk[8];
    __shared__ float bq, bk;
    const int warp = tid >> 5, lane = tid & 31;
    if (lane == 0) { wq[warp] = sq; wk[warp] = sk; }
    __syncthreads();
    if (tid == 0) {
        float aq = 0.0f, ak = 0.0f;
#pragma unroll
        for (int i = 0; i < 8; ++i) { aq += wq[i]; ak += wk[i]; }
        bq = rsqrtf(aq * (1.0f / 1024.0f) + RMSEPS);
        bk = rsqrtf(ak * (1.0f / 1024.0f) + RMSEPS);
    }
    __syncthreads();
    const float scq = bq, sck = bk;
    const int c0 = tid * 4;
    float qe[4] = {q.x, q.y, q.z, q.w};
    float ke[4] = {k.x, k.y, k.z, k.w};
#pragma unroll
    for (int i = 0; i < 4; ++i) {
        qe[i] *= scq * gq[c0 + i];
        ke[i] *= sck * gk[c0 + i];
    }
#pragma unroll
    for (int p = 0; p < 2; ++p) {
        int d = (c0 + 2 * p) & 63;        // even index within head
        int j = d >> 1;
        float c = g_cos[l * 32 + j];
        float s = g_sin[l * 32 + j];
        float q0 = qe[2*p], q1 = qe[2*p + 1];
        qe[2*p]     = q0 * c - q1 * s;
        qe[2*p + 1] = q0 * s + q1 * c;
        float k0 = ke[2*p], k1 = ke[2*p + 1];
        ke[2*p]     = k0 * c - k1 * s;
        ke[2*p + 1] = k0 * s + k1 * c;
    }
    float4 qo = make_float4(fmaxf(qe[0],0.f), fmaxf(qe[1],0.f), fmaxf(qe[2],0.f), fmaxf(qe[3],0.f));
    float4 ko = make_float4(fmaxf(ke[0],0.f), fmaxf(ke[1],0.f), fmaxf(ke[2],0.f), fmaxf(ke[3],0.f));
    *(float4*)(row + tid * 4)      = qo;
    *(float4*)(row + Dq + tid * 4) = ko;
}

// ---------------------------------------------------------------------------
// K3: vk partials. CTA = (b*H+h, Lchunk of 256 tokens). No atomics.
// vk[p,d] = sum_l vpad[l,p]*kf[l,d], p=64 row is sum of kf.
// ---------------------------------------------------------------------------
__global__ __launch_bounds__(256) void vk_accum_k() {
    const int bh = blockIdx.x;        // 0..63
    const int chunk = blockIdx.y;     // 0..15
    const int b = bh >> 4, h = bh & 15;
    const int tid = threadIdx.x;
    __shared__ __align__(16) float kf_s[32 * 64];
    __shared__ __align__(16) float vp_s[32 * 65];
    float acc[17];
#pragma unroll
    for (int i = 0; i < 17; ++i) acc[i] = 0.0f;
    if (tid < 32) vp_s[tid * 65 + 64] = 1.0f;   // vpad ones column
    const int tok0 = b * Lq + chunk * 256;
    const int r0 = tid >> 4;
    const int c4 = (tid & 15) << 2;
    for (int sub = 0; sub < 8; ++sub) {
        const int tbase = tok0 + sub * 32;
#pragma unroll
        for (int half = 0; half < 2; ++half) {
            int r = r0 + half * 16;
            const float* src = g_qkv + (size_t)(tbase + r) * NQKV + h * DHq + c4;
            float4 kv = *(const float4*)(src + Dq);       // kf
            float4 vv = *(const float4*)(src + 2 * Dq);   // v
            *(float4*)&kf_s[r * 64 + c4] = kv;
            vp_s[r * 65 + c4 + 0] = vv.x;
            vp_s[r * 65 + c4 + 1] = vv.y;
            vp_s[r * 65 + c4 + 2] = vv.z;
            vp_s[r * 65 + c4 + 3] = vv.w;
        }
        __syncthreads();
#pragma unroll
        for (int ei = 0; ei < 17; ++ei) {
            const int e = tid + ei * 256;
            if (e < 65 * 64) {
                const int p = e >> 6, dd = e & 63;
                float a = acc[ei];
#pragma unroll
                for (int r = 0; r < 32; ++r)
                    a = fmaf(vp_s[r * 65 + p], kf_s[r * 64 + dd], a);
                acc[ei] = a;
            }
        }
        __syncthreads();
    }
#pragma unroll
    for (int ei = 0; ei < 17; ++ei) {
        const int e = tid + ei * 256;
        if (e < 65 * 64)
            g_vkp[(size_t)chunk * (64 * 65 * 64) + bh * (65 * 64) + e] = acc[ei];
    }
}

// K4: deterministic fixed-order reduce of the 16 L-chunk partials.
__global__ void vk_reduce_k() {
    int i = blockIdx.x * 256 + threadIdx.x;    // over 64*4160
    if (i >= 64 * 65 * 64) return;
    float s = 0.0f;
#pragma unroll
    for (int c = 0; c < 16; ++c) s += g_vkp[(size_t)c * (64 * 65 * 64) + i];
    g_vk[i] = s;
}

// ---------------------------------------------------------------------------
// K5: res = vk . qf ; attn = res[:64]/(res[64]+eps). CTA = (bh, 64-token tile).
// ---------------------------------------------------------------------------
__global__ __launch_bounds__(256) void attn_apply_k() {
    const int bh = blockIdx.x;   // 64
    const int lt = blockIdx.y;   // 64
    const int b = bh >> 4, h = bh & 15;
    const int tid = threadIdx.x;
    __shared__ __align__(16) float qf_s[64 * 64];   // first: keeps vk_s alignment irrelevant
    __shared__ __align__(16) float vk_s[65 * 65];   // row p padded to 65 (conflict-free d-major reads)
#pragma unroll
    for (int ei = 0; ei < 17; ++ei) {
        int e = tid + ei * 256;
        if (e < 65 * 64) vk_s[(e >> 6) * 65 + (e & 63)] = g_vk[bh * (65 * 64) + e];
    }
    const int tok0 = b * Lq + lt * 64;
#pragma unroll
    for (int pass = 0; pass < 4; ++pass) {
        int fi = tid + pass * 256;             // float4 index 0..1023
        int r = fi >> 4, c4 = (fi & 15) << 2;
        float4 v = *(const float4*)(g_qkv + (size_t)(tok0 + r) * NQKV + h * DHq + c4);
        *(float4*)&qf_s[r * 64 + c4] = v;
    }
    __syncthreads();
    const int dd = tid & 63;
    const int tsub = tid >> 6;                 // 0..3
#pragma unroll 4
    for (int it = 0; it < 16; ++it) {
        const int tok = it * 4 + tsub;
        float num = 0.0f, den = 0.0f;
#pragma unroll
        for (int k = 0; k < 64; ++k) {
            float qv = qf_s[tok * 64 + k];
            num = fmaf(vk_s[dd * 65 + k], qv, num);
            den = fmaf(vk_s[64 * 65 + k], qv, den);
        }
        float o = num / (den + EPSLIN);
        const int lpos = lt * 64 + tok;
        g_attn[(size_t)(b * Lq + lpos) * Dq + h * DHq + dd] = o;
    }
}

// ---------------------------------------------------------------------------
// K7: final rmsnorm over g_y rows -> d_out
// ---------------------------------------------------------------------------
__global__ __launch_bounds__(256) void out_rms_k(const float* __restrict__ gout,
                                                 float* __restrict__ out)
{
    const int t = blockIdx.x;
    const int tid = threadIdx.x;
    const float* row = g_y + (size_t)t * Dq;
    float4 y = *(const float4*)(row + tid * 4);
    float ss = y.x*y.x + y.y*y.y + y.z*y.z + y.w*y.w;
#pragma unroll
    for (int o = 16; o > 0; o >>= 1) ss += __shfl_xor_sync(0xffffffffu, ss, o);
    __shared__ float w[8];
    __shared__ float bsc;
    if ((tid & 31) == 0) w[tid >> 5] = ss;
    __syncthreads();
    if (tid == 0) {
        float a = 0.0f;
#pragma unroll
        for (int i = 0; i < 8; ++i) a += w[i];
        bsc = rsqrtf(a * (1.0f / 1024.0f) + RMSEPS);
    }
    __syncthreads();
    const float sc = bsc;
    const int c0 = tid * 4;
    float4 o4;
    o4.x = y.x * sc * gout[c0 + 0];
    o4.y = y.y * sc * gout[c0 + 1];
    o4.z = y.z * sc * gout[c0 + 2];
    o4.w = y.w * sc * gout[c0 + 3];
    *(float4*)(out + (size_t)t * Dq + c0) = o4;
}

// ---------------------------------------------------------------------------
extern "C" void kernel_launch(void* const* d_in, const int* in_sizes, int n_in,
                              void* d_out, int out_size) {
    (void)in_sizes; (void)n_in; (void)out_size;
    const float* x    = (const float*)d_in[0];
    const float* Wqkv = (const float*)d_in[1];
    const float* bqkv = (const float*)d_in[2];
    const float* gq   = (const float*)d_in[3];
    const float* gk   = (const float*)d_in[4];
    const float* Wout = (const float*)d_in[5];
    const float* bout = (const float*)d_in[6];
    const float* gout = (const float*)d_in[7];
    float* out = (float*)d_out;

    float *qkv_p, *attn_p, *y_p;
    cudaGetSymbolAddress((void**)&qkv_p,  g_qkv);
    cudaGetSymbolAddress((void**)&attn_p, g_attn);
    cudaGetSymbolAddress((void**)&y_p,    g_y);

    rope_tables_k<<<(Lq * 32 + 255) / 256, 256>>>();
    gemm_tn_k<<<dim3(NQKV / 128, MTOK / 128), 256>>>(x, Wqkv, bqkv, qkv_p, NQKV, Dq);
    qk_prep_k<<<MTOK, 256>>>(gq, gk);
    vk_accum_k<<<dim3(64, 16), 256>>>();
    vk_reduce_k<<<(64 * 65 * 64 + 255) / 256, 256>>>();
    attn_apply_k<<<dim3(64, 64), 256>>>();
    gemm_tn_k<<<dim3(Dq / 128, MTOK / 128), 256>>>(attn_p, Wout, bout, y_p, Dq, Dq);
    out_rms_k<<<MTOK, 256>>>(gout, out);
}

// round 4
// speedup vs baseline: 1.7463x; 1.7463x over previous
#include <cuda_runtime.h>
#include <cuda_bf16.h>
#include <math.h>
#include <stdint.h>

// Problem constants
#define Bq    4
#define Lq    4096
#define Dq    1024
#define Hq    16
#define DHq   64
#define MTOK  (Bq*Lq)      // 16384
#define NQKV  (3*Dq)       // 3072
#define RMSEPS 1.1920929e-07f
#define EPSLIN 1e-06f

// Scratch (device globals — no allocation allowed)
__device__ __align__(256) float g_qkv [(size_t)MTOK * NQKV];
__device__ __align__(256) float g_vkp [16 * 64 * 65 * DHq];
__device__ __align__(256) float g_vk  [64 * 65 * DHq];
__device__ __align__(256) float g_attn[(size_t)MTOK * Dq];
__device__ __align__(256) float g_y   [(size_t)MTOK * Dq];
__device__ __align__(256) float g_cos [Lq * 32];
__device__ __align__(256) float g_sin [Lq * 32];
// bf16 hi/lo operand buffers
__device__ __align__(256) __nv_bfloat16 g_xhi [(size_t)MTOK * Dq];
__device__ __align__(256) __nv_bfloat16 g_xlo [(size_t)MTOK * Dq];
__device__ __align__(256) __nv_bfloat16 g_whi1[(size_t)NQKV * Dq];
__device__ __align__(256) __nv_bfloat16 g_wlo1[(size_t)NQKV * Dq];
__device__ __align__(256) __nv_bfloat16 g_whi2[(size_t)Dq * Dq];
__device__ __align__(256) __nv_bfloat16 g_wlo2[(size_t)Dq * Dq];
__device__ __align__(256) __nv_bfloat16 g_ahi [(size_t)MTOK * Dq];
__device__ __align__(256) __nv_bfloat16 g_alo [(size_t)MTOK * Dq];

// ---------------------------------------------------------------------------
// K0: RoPE tables
// ---------------------------------------------------------------------------
__global__ void rope_tables_k() {
    int idx = blockIdx.x * blockDim.x + threadIdx.x;
    if (idx >= Lq * 32) return;
    int l = idx >> 5, j = idx & 31;
    float inv_freq = expf(-(float)j * (9.210340371976184f / 32.0f));
    float ang = (float)l * inv_freq;
    g_cos[idx] = cosf(ang);
    g_sin[idx] = sinf(ang);
}

// ---------------------------------------------------------------------------
// fp32 -> bf16 hi/lo split
// ---------------------------------------------------------------------------
__global__ __launch_bounds__(256) void split_bf16_k(
    const float* __restrict__ s, __nv_bfloat16* __restrict__ hi,
    __nv_bfloat16* __restrict__ lo, int n4)
{
    int i = blockIdx.x * 256 + threadIdx.x;
    if (i >= n4) return;
    float4 v = ((const float4*)s)[i];
    __nv_bfloat162 h0 = __floats2bfloat162_rn(v.x, v.y);
    __nv_bfloat162 h1 = __floats2bfloat162_rn(v.z, v.w);
    float r0 = v.x - __bfloat162float(h0.x);
    float r1 = v.y - __bfloat162float(h0.y);
    float r2 = v.z - __bfloat162float(h1.x);
    float r3 = v.w - __bfloat162float(h1.y);
    __nv_bfloat162 l0 = __floats2bfloat162_rn(r0, r1);
    __nv_bfloat162 l1 = __floats2bfloat162_rn(r2, r3);
    ((__nv_bfloat162*)hi)[2*i]   = h0;
    ((__nv_bfloat162*)hi)[2*i+1] = h1;
    ((__nv_bfloat162*)lo)[2*i]   = l0;
    ((__nv_bfloat162*)lo)[2*i+1] = l1;
}

// ---------------------------------------------------------------------------
// HMMA GEMM: C[m,n] = sum_k A[m,k]*B[n,k] + bias[n], K=1024.
// Tile 128x128, 256 threads (8 warps as 4(m) x 2(n)), warp tile 32x64.
// mma.sync.m16n8k16 bf16, 3 passes (Ah*Bh + Ah*Bl + Al*Bh).
// Smem pitch 72B (64B data + 8B pad) to dodge bank conflicts.
// ---------------------------------------------------------------------------
#define BKS    32                   // K per slab
#define NSLAB  32                   // 1024/32
#define PITCHB 72                   // bytes per smem row (32 bf16 + pad)
#define ASZ    (128 * PITCHB)       // one operand tile: 9216 B
#define STAGE  (4 * ASZ)            // Ah, Al, Bh, Bl: 36864 B

__device__ __forceinline__ void mma_bf16(float* c, const uint32_t* a, const uint32_t* b) {
    asm volatile(
        "mma.sync.aligned.m16n8k16.row.col.f32.bf16.bf16.f32 "
        "{%0,%1,%2,%3}, {%4,%5,%6,%7}, {%8,%9}, {%0,%1,%2,%3};"
        : "+f"(c[0]), "+f"(c[1]), "+f"(c[2]), "+f"(c[3])
        : "r"(a[0]), "r"(a[1]), "r"(a[2]), "r"(a[3]), "r"(b[0]), "r"(b[1]));
}

__global__ __launch_bounds__(256, 1)
void gemm_hmma_k(const __nv_bfloat16* __restrict__ Ah, const __nv_bfloat16* __restrict__ Al,
                 const __nv_bfloat16* __restrict__ Bh, const __nv_bfloat16* __restrict__ Bl,
                 const float* __restrict__ bias, float* __restrict__ C, int N)
{
    extern __shared__ __align__(16) char sm[];
    const int tid  = threadIdx.x;
    const int wid  = tid >> 5, lane = tid & 31;
    const int wm   = wid & 3, wn = wid >> 2;     // 4 x 2 warps
    const int g    = lane >> 2, t = lane & 3;
    const int m0   = blockIdx.y * 128;
    const int n0   = blockIdx.x * 128;

    const __nv_bfloat16* tp[4] = {Ah, Al, Bh, Bl};

    float acc[2][8][4];
#pragma unroll
    for (int mf = 0; mf < 2; ++mf)
#pragma unroll
        for (int nf = 0; nf < 8; ++nf)
#pragma unroll
            for (int e = 0; e < 4; ++e) acc[mf][nf][e] = 0.0f;

    uint4 r[8];
    auto ldg_slab = [&](int ks) {
#pragma unroll
        for (int j = 0; j < 8; ++j) {
            int c = j * 256 + tid;
            int tile = c >> 9, w = c & 511;
            int row = w >> 2, c4 = w & 3;
            int rb = (tile < 2) ? m0 : n0;
            r[j] = *(const uint4*)(tp[tile] + (size_t)(rb + row) * 1024 + ks * BKS + c4 * 8);
        }
    };
    auto sts_slab = [&](int st) {
        char* base = sm + st * STAGE;
#pragma unroll
        for (int j = 0; j < 8; ++j) {
            int c = j * 256 + tid;
            int tile = c >> 9, w = c & 511;
            int row = w >> 2, c4 = w & 3;
            char* d = base + tile * ASZ + row * PITCHB + c4 * 16;
            *(uint2*)d       = make_uint2(r[j].x, r[j].y);
            *(uint2*)(d + 8) = make_uint2(r[j].z, r[j].w);
        }
    };

    // A fragment rows for this warp: wm*32 + mf*16 + g (+8); B rows: wn*64 + nf*8 + g
    const int ar0 = wm * 32 + g;
    const int bn0 = wn * 64 + g;

    ldg_slab(0);
#pragma unroll 1
    for (int i = 0; i < NSLAB; ++i) {
        sts_slab(i & 1);
        __syncthreads();
        if (i < NSLAB - 1) ldg_slab(i + 1);

        const char* st = sm + (i & 1) * STAGE;
        const char* pAh = st;
        const char* pAl = st + ASZ;
        const char* pBh = st + 2 * ASZ;
        const char* pBl = st + 3 * ASZ;
#pragma unroll
        for (int kk = 0; kk < 2; ++kk) {            // k = kk*16
            const int kb = (kk * 16 + 2 * t) * 2;   // byte offset of k pair
            uint32_t ah[2][4], al[2][4];
#pragma unroll
            for (int mf = 0; mf < 2; ++mf) {
                int rA = (ar0 + mf * 16) * PITCHB;
                int rA8 = rA + 8 * PITCHB;
                ah[mf][0] = *(const uint32_t*)(pAh + rA  + kb);
                ah[mf][1] = *(const uint32_t*)(pAh + rA8 + kb);
                ah[mf][2] = *(const uint32_t*)(pAh + rA  + kb + 16);
                ah[mf][3] = *(const uint32_t*)(pAh + rA8 + kb + 16);
                al[mf][0] = *(const uint32_t*)(pAl + rA  + kb);
                al[mf][1] = *(const uint32_t*)(pAl + rA8 + kb);
                al[mf][2] = *(const uint32_t*)(pAl + rA  + kb + 16);
                al[mf][3] = *(const uint32_t*)(pAl + rA8 + kb + 16);
            }
#pragma unroll
            for (int nf = 0; nf < 8; ++nf) {
                int rB = (bn0 + nf * 8) * PITCHB;
                uint32_t bh[2], bl[2];
                bh[0] = *(const uint32_t*)(pBh + rB + kb);
                bh[1] = *(const uint32_t*)(pBh + rB + kb + 16);
                bl[0] = *(const uint32_t*)(pBl + rB + kb);
                bl[1] = *(const uint32_t*)(pBl + rB + kb + 16);
#pragma unroll
                for (int mf = 0; mf < 2; ++mf) {
                    mma_bf16(acc[mf][nf], ah[mf], bh);
                    mma_bf16(acc[mf][nf], ah[mf], bl);
                    mma_bf16(acc[mf][nf], al[mf], bh);
                }
            }
        }
        __syncthreads();
    }

    // Epilogue: bias add + store (float2 per fragment row)
#pragma unroll
    for (int mf = 0; mf < 2; ++mf) {
        int row = m0 + wm * 32 + mf * 16 + g;
#pragma unroll
        for (int nf = 0; nf < 8; ++nf) {
            int col = n0 + wn * 64 + nf * 8 + 2 * t;
            float b0 = bias[col], b1 = bias[col + 1];
            float2 o0 = make_float2(acc[mf][nf][0] + b0, acc[mf][nf][1] + b1);
            float2 o1 = make_float2(acc[mf][nf][2] + b0, acc[mf][nf][3] + b1);
            *(float2*)(C + (size_t)row * N + col)       = o0;
            *(float2*)(C + (size_t)(row + 8) * N + col) = o1;
        }
    }
}

// ---------------------------------------------------------------------------
// K2: per-token rmsnorm(q), rmsnorm(k), RoPE, ReLU — in place in g_qkv.
// ---------------------------------------------------------------------------
__global__ __launch_bounds__(256) void qk_prep_k(const float* __restrict__ gq,
                                                 const float* __restrict__ gk)
{
    const int t = blockIdx.x;
    const int l = t & (Lq - 1);
    const int tid = threadIdx.x;
    float* row = g_qkv + (size_t)t * NQKV;
    float4 q = *(float4*)(row + tid * 4);
    float4 k = *(float4*)(row + Dq + tid * 4);
    float sq = q.x*q.x + q.y*q.y + q.z*q.z + q.w*q.w;
    float sk = k.x*k.x + k.y*k.y + k.z*k.z + k.w*k.w;
#pragma unroll
    for (int o = 16; o > 0; o >>= 1) {
        sq += __shfl_xor_sync(0xffffffffu, sq, o);
        sk += __shfl_xor_sync(0xffffffffu, sk, o);
    }
    __shared__ float wq[8], wk[8];
    __shared__ float bq, bk;
    const int warp = tid >> 5, lane = tid & 31;
    if (lane == 0) { wq[warp] = sq; wk[warp] = sk; }
    __syncthreads();
    if (tid == 0) {
        float aq = 0.0f, ak = 0.0f;
#pragma unroll
        for (int i = 0; i < 8; ++i) { aq += wq[i]; ak += wk[i]; }
        bq = rsqrtf(aq * (1.0f / 1024.0f) + RMSEPS);
        bk = rsqrtf(ak * (1.0f / 1024.0f) + RMSEPS);
    }
    __syncthreads();
    const float scq = bq, sck = bk;
    const int c0 = tid * 4;
    float qe[4] = {q.x, q.y, q.z, q.w};
    float ke[4] = {k.x, k.y, k.z, k.w};
#pragma unroll
    for (int i = 0; i < 4; ++i) {
        qe[i] *= scq * gq[c0 + i];
        ke[i] *= sck * gk[c0 + i];
    }
#pragma unroll
    for (int p = 0; p < 2; ++p) {
        int d = (c0 + 2 * p) & 63;
        int j = d >> 1;
        float c = g_cos[l * 32 + j];
        float s = g_sin[l * 32 + j];
        float q0 = qe[2*p], q1 = qe[2*p + 1];
        qe[2*p]     = q0 * c - q1 * s;
        qe[2*p + 1] = q0 * s + q1 * c;
        float k0 = ke[2*p], k1 = ke[2*p + 1];
        ke[2*p]     = k0 * c - k1 * s;
        ke[2*p + 1] = k0 * s + k1 * c;
    }
    float4 qo = make_float4(fmaxf(qe[0],0.f), fmaxf(qe[1],0.f), fmaxf(qe[2],0.f), fmaxf(qe[3],0.f));
    float4 ko = make_float4(fmaxf(ke[0],0.f), fmaxf(ke[1],0.f), fmaxf(ke[2],0.f), fmaxf(ke[3],0.f));
    *(float4*)(row + tid * 4)      = qo;
    *(float4*)(row + Dq + tid * 4) = ko;
}

// ---------------------------------------------------------------------------
// K3: vk partials. CTA = (b*H+h, Lchunk of 256 tokens).
// ---------------------------------------------------------------------------
__global__ __launch_bounds__(256) void vk_accum_k() {
    const int bh = blockIdx.x;
    const int chunk = blockIdx.y;
    const int b = bh >> 4, h = bh & 15;
    const int tid = threadIdx.x;
    __shared__ __align__(16) float kf_s[32 * 64];
    __shared__ __align__(16) float vp_s[32 * 65];
    float acc[17];
#pragma unroll
    for (int i = 0; i < 17; ++i) acc[i] = 0.0f;
    if (tid < 32) vp_s[tid * 65 + 64] = 1.0f;
    const int tok0 = b * Lq + chunk * 256;
    const int r0 = tid >> 4;
    const int c4 = (tid & 15) << 2;
    for (int sub = 0; sub < 8; ++sub) {
        const int tbase = tok0 + sub * 32;
#pragma unroll
        for (int half = 0; half < 2; ++half) {
            int r = r0 + half * 16;
            const float* src = g_qkv + (size_t)(tbase + r) * NQKV + h * DHq + c4;
            float4 kv = *(const float4*)(src + Dq);
            float4 vv = *(const float4*)(src + 2 * Dq);
            *(float4*)&kf_s[r * 64 + c4] = kv;
            vp_s[r * 65 + c4 + 0] = vv.x;
            vp_s[r * 65 + c4 + 1] = vv.y;
            vp_s[r * 65 + c4 + 2] = vv.z;
            vp_s[r * 65 + c4 + 3] = vv.w;
        }
        __syncthreads();
#pragma unroll
        for (int ei = 0; ei < 17; ++ei) {
            const int e = tid + ei * 256;
            if (e < 65 * 64) {
                const int p = e >> 6, dd = e & 63;
                float a = acc[ei];
#pragma unroll
                for (int r = 0; r < 32; ++r)
                    a = fmaf(vp_s[r * 65 + p], kf_s[r * 64 + dd], a);
                acc[ei] = a;
            }
        }
        __syncthreads();
    }
#pragma unroll
    for (int ei = 0; ei < 17; ++ei) {
        const int e = tid + ei * 256;
        if (e < 65 * 64)
            g_vkp[(size_t)chunk * (64 * 65 * 64) + bh * (65 * 64) + e] = acc[ei];
    }
}

// K4: deterministic reduce of the 16 L-chunk partials.
__global__ void vk_reduce_k() {
    int i = blockIdx.x * 256 + threadIdx.x;
    if (i >= 64 * 65 * 64) return;
    float s = 0.0f;
#pragma unroll
    for (int c = 0; c < 16; ++c) s += g_vkp[(size_t)c * (64 * 65 * 64) + i];
    g_vk[i] = s;
}

// ---------------------------------------------------------------------------
// K5: res = vk . qf ; attn = res[:64]/(res[64]+eps)
// ---------------------------------------------------------------------------
__global__ __launch_bounds__(256) void attn_apply_k() {
    const int bh = blockIdx.x;
    const int lt = blockIdx.y;
    const int b = bh >> 4, h = bh & 15;
    const int tid = threadIdx.x;
    __shared__ __align__(16) float qf_s[64 * 64];
    __shared__ __align__(16) float vk_s[65 * 65];
#pragma unroll
    for (int ei = 0; ei < 17; ++ei) {
        int e = tid + ei * 256;
        if (e < 65 * 64) vk_s[(e >> 6) * 65 + (e & 63)] = g_vk[bh * (65 * 64) + e];
    }
    const int tok0 = b * Lq + lt * 64;
#pragma unroll
    for (int pass = 0; pass < 4; ++pass) {
        int fi = tid + pass * 256;
        int r = fi >> 4, c4 = (fi & 15) << 2;
        float4 v = *(const float4*)(g_qkv + (size_t)(tok0 + r) * NQKV + h * DHq + c4);
        *(float4*)&qf_s[r * 64 + c4] = v;
    }
    __syncthreads();
    const int dd = tid & 63;
    const int tsub = tid >> 6;
#pragma unroll 4
    for (int it = 0; it < 16; ++it) {
        const int tok = it * 4 + tsub;
        float num = 0.0f, den = 0.0f;
#pragma unroll
        for (int k = 0; k < 64; ++k) {
            float qv = qf_s[tok * 64 + k];
            num = fmaf(vk_s[dd * 65 + k], qv, num);
            den = fmaf(vk_s[64 * 65 + k], qv, den);
        }
        float o = num / (den + EPSLIN);
        const int lpos = lt * 64 + tok;
        g_attn[(size_t)(b * Lq + lpos) * Dq + h * DHq + dd] = o;
    }
}

// ---------------------------------------------------------------------------
// K7: final rmsnorm over g_y rows -> d_out
// ---------------------------------------------------------------------------
__global__ __launch_bounds__(256) void out_rms_k(const float* __restrict__ gout,
                                                 float* __restrict__ out)
{
    const int t = blockIdx.x;
    const int tid = threadIdx.x;
    const float* row = g_y + (size_t)t * Dq;
    float4 y = *(const float4*)(row + tid * 4);
    float ss = y.x*y.x + y.y*y.y + y.z*y.z + y.w*y.w;
#pragma unroll
    for (int o = 16; o > 0; o >>= 1) ss += __shfl_xor_sync(0xffffffffu, ss, o);
    __shared__ float w[8];
    __shared__ float bsc;
    if ((tid & 31) == 0) w[tid >> 5] = ss;
    __syncthreads();
    if (tid == 0) {
        float a = 0.0f;
#pragma unroll
        for (int i = 0; i < 8; ++i) a += w[i];
        bsc = rsqrtf(a * (1.0f / 1024.0f) + RMSEPS);
    }
    __syncthreads();
    const float sc = bsc;
    const int c0 = tid * 4;
    float4 o4;
    o4.x = y.x * sc * gout[c0 + 0];
    o4.y = y.y * sc * gout[c0 + 1];
    o4.z = y.z * sc * gout[c0 + 2];
    o4.w = y.w * sc * gout[c0 + 3];
    *(float4*)(out + (size_t)t * Dq + c0) = o4;
}

// ---------------------------------------------------------------------------
extern "C" void kernel_launch(void* const* d_in, const int* in_sizes, int n_in,
                              void* d_out, int out_size) {
    (void)in_sizes; (void)n_in; (void)out_size;
    const float* x    = (const float*)d_in[0];
    const float* Wqkv = (const float*)d_in[1];
    const float* bqkv = (const float*)d_in[2];
    const float* gq   = (const float*)d_in[3];
    const float* gk   = (const float*)d_in[4];
    const float* Wout = (const float*)d_in[5];
    const float* bout = (const float*)d_in[6];
    const float* gout = (const float*)d_in[7];
    float* out = (float*)d_out;

    float *qkv_p, *attn_p, *y_p;
    __nv_bfloat16 *xhi, *xlo, *whi1, *wlo1, *whi2, *wlo2, *ahi, *alo;
    cudaGetSymbolAddress((void**)&qkv_p,  g_qkv);
    cudaGetSymbolAddress((void**)&attn_p, g_attn);
    cudaGetSymbolAddress((void**)&y_p,    g_y);
    cudaGetSymbolAddress((void**)&xhi,  g_xhi);
    cudaGetSymbolAddress((void**)&xlo,  g_xlo);
    cudaGetSymbolAddress((void**)&whi1, g_whi1);
    cudaGetSymbolAddress((void**)&wlo1, g_wlo1);
    cudaGetSymbolAddress((void**)&whi2, g_whi2);
    cudaGetSymbolAddress((void**)&wlo2, g_wlo2);
    cudaGetSymbolAddress((void**)&ahi,  g_ahi);
    cudaGetSymbolAddress((void**)&alo,  g_alo);

    const int DSMEM = 2 * STAGE;   // 73728 B
    cudaFuncSetAttribute(gemm_hmma_k, cudaFuncAttributeMaxDynamicSharedMemorySize, DSMEM);

    rope_tables_k<<<(Lq * 32 + 255) / 256, 256>>>();
    split_bf16_k<<<(MTOK * Dq / 4 + 255) / 256, 256>>>(x,    xhi,  xlo,  MTOK * Dq / 4);
    split_bf16_k<<<(NQKV * Dq / 4 + 255) / 256, 256>>>(Wqkv, whi1, wlo1, NQKV * Dq / 4);
    split_bf16_k<<<(Dq * Dq / 4 + 255) / 256, 256>>>(Wout,   whi2, wlo2, Dq * Dq / 4);

    gemm_hmma_k<<<dim3(NQKV / 128, MTOK / 128), 256, DSMEM>>>(
        xhi, xlo, whi1, wlo1, bqkv, qkv_p, NQKV);

    qk_prep_k<<<MTOK, 256>>>(gq, gk);
    vk_accum_k<<<dim3(64, 16), 256>>>();
    vk_reduce_k<<<(64 * 65 * 64 + 255) / 256, 256>>>();
    attn_apply_k<<<dim3(64, 64), 256>>>();

    split_bf16_k<<<(MTOK * Dq / 4 + 255) / 256, 256>>>(attn_p, ahi, alo, MTOK * Dq / 4);
    gemm_hmma_k<<<dim3(Dq / 128, MTOK / 128), 256, DSMEM>>>(
        ahi, alo, whi2, wlo2, bout, y_p, Dq);

    out_rms_k<<<MTOK, 256>>>(gout, out);
}

// round 5
// speedup vs baseline: 2.6429x; 1.5135x over previous
#include <cuda_runtime.h>
#include <cuda_fp16.h>
#include <math.h>
#include <stdint.h>

// Problem constants
#define Bq    4
#define Lq    4096
#define Dq    1024
#define Hq    16
#define DHq   64
#define MTOK  (Bq*Lq)      // 16384
#define NQKV  (3*Dq)       // 3072
#define RMSEPS 1.1920929e-07f
#define EPSLIN 1e-06f

// Scratch (device globals — no allocation allowed)
__device__ __align__(256) float g_qkv [(size_t)MTOK * NQKV];
__device__ __align__(256) float g_vkp [16 * 64 * 65 * DHq];
__device__ __align__(256) float g_vk  [64 * 65 * DHq];
__device__ __align__(256) float g_attn[(size_t)MTOK * Dq];
__device__ __align__(256) float g_y   [(size_t)MTOK * Dq];
__device__ __align__(256) float g_cos [Lq * 32];
__device__ __align__(256) float g_sin [Lq * 32];
// fp16 operands
__device__ __align__(256) __half g_xh [(size_t)MTOK * Dq];
__device__ __align__(256) __half g_ah [(size_t)MTOK * Dq];
__device__ __align__(256) __half g_wh1[(size_t)NQKV * Dq];
__device__ __align__(256) __half g_wl1[(size_t)NQKV * Dq];
__device__ __align__(256) __half g_wh2[(size_t)Dq * Dq];
__device__ __align__(256) __half g_wl2[(size_t)Dq * Dq];

// ---------------------------------------------------------------------------
__device__ __forceinline__ uint32_t smem_u32(const void* p) {
    uint32_t a;
    asm("{ .reg .u64 t; cvta.to.shared.u64 t, %1; cvt.u32.u64 %0, t; }" : "=r"(a) : "l"(p));
    return a;
}
__device__ __forceinline__ void cp_async16(uint32_t dst, const void* src) {
    asm volatile("cp.async.cg.shared.global [%0], [%1], 16;" :: "r"(dst), "l"(src));
}
#define CP_COMMIT() asm volatile("cp.async.commit_group;" ::: "memory")
template <int N>
__device__ __forceinline__ void cp_wait() {
    asm volatile("cp.async.wait_group %0;" :: "n"(N) : "memory");
}
__device__ __forceinline__ void ldm_x4(uint32_t* r, uint32_t addr) {
    asm volatile("ldmatrix.sync.aligned.m8n8.x4.shared.b16 {%0,%1,%2,%3}, [%4];"
                 : "=r"(r[0]), "=r"(r[1]), "=r"(r[2]), "=r"(r[3]) : "r"(addr));
}
__device__ __forceinline__ void mma_f16(float* c, const uint32_t* a, const uint32_t* b) {
    asm volatile(
        "mma.sync.aligned.m16n8k16.row.col.f32.f16.f16.f32 "
        "{%0,%1,%2,%3}, {%4,%5,%6,%7}, {%8,%9}, {%0,%1,%2,%3};"
        : "+f"(c[0]), "+f"(c[1]), "+f"(c[2]), "+f"(c[3])
        : "r"(a[0]), "r"(a[1]), "r"(a[2]), "r"(a[3]), "r"(b[0]), "r"(b[1]));
}

// ---------------------------------------------------------------------------
// K0: RoPE tables
// ---------------------------------------------------------------------------
__global__ void rope_tables_k() {
    int idx = blockIdx.x * blockDim.x + threadIdx.x;
    if (idx >= Lq * 32) return;
    int l = idx >> 5, j = idx & 31;
    float inv_freq = expf(-(float)j * (9.210340371976184f / 32.0f));
    float ang = (float)l * inv_freq;
    g_cos[idx] = cosf(ang);
    g_sin[idx] = sinf(ang);
}

// fp32 -> fp16 (single)
__global__ __launch_bounds__(256) void to_half_k(
    const float* __restrict__ s, __half* __restrict__ d, int n4)
{
    int i = blockIdx.x * 256 + threadIdx.x;
    if (i >= n4) return;
    float4 v = ((const float4*)s)[i];
    __half2 h0 = __floats2half2_rn(v.x, v.y);
    __half2 h1 = __floats2half2_rn(v.z, v.w);
    ((__half2*)d)[2*i]   = h0;
    ((__half2*)d)[2*i+1] = h1;
}

// fp32 -> fp16 hi/lo split
__global__ __launch_bounds__(256) void split_half_k(
    const float* __restrict__ s, __half* __restrict__ hi,
    __half* __restrict__ lo, int n4)
{
    int i = blockIdx.x * 256 + threadIdx.x;
    if (i >= n4) return;
    float4 v = ((const float4*)s)[i];
    __half2 h0 = __floats2half2_rn(v.x, v.y);
    __half2 h1 = __floats2half2_rn(v.z, v.w);
    float r0 = v.x - __half2float(__low2half(h0));
    float r1 = v.y - __half2float(__high2half(h0));
    float r2 = v.z - __half2float(__low2half(h1));
    float r3 = v.w - __half2float(__high2half(h1));
    ((__half2*)hi)[2*i]   = h0;
    ((__half2*)hi)[2*i+1] = h1;
    ((__half2*)lo)[2*i]   = __floats2half2_rn(r0, r1);
    ((__half2*)lo)[2*i+1] = __floats2half2_rn(r2, r3);
}

// ---------------------------------------------------------------------------
// HMMA GEMM v2: C[m,n] = sum_k A[m,k]*B[n,k] + bias[n], K = 1024.
// A single fp16; B = Bh + Bl fp16 (2 accumulation passes).
// Tile 128x128, 256 thr (8 warps = 4m x 2n, warp tile 32x64).
// cp.async 4-stage pipeline; ldmatrix.x4 fragments; smem pitch 80B.
// ---------------------------------------------------------------------------
#define BKS     32
#define NSLAB   32                  // 1024/32
#define PITCH   80                  // bytes per row (64B data + 16B pad)
#define TILEB   (128 * PITCH)       // 10240
#define OFF_BH  TILEB
#define OFF_BL  (2 * TILEB)
#define STAGE   (3 * TILEB)         // 30720
#define NSTG    4

__global__ __launch_bounds__(256, 1)
void gemm_hmma2_k(const __half* __restrict__ A, const __half* __restrict__ Bh,
                  const __half* __restrict__ Bl, const float* __restrict__ bias,
                  float* __restrict__ C, int N)
{
    extern __shared__ __align__(16) char sm[];
    const uint32_t smb = smem_u32(sm);
    const int tid  = threadIdx.x;
    const int wid  = tid >> 5, lane = tid & 31;
    const int wm   = wid & 3, wn = wid >> 2;
    const int g    = lane >> 2, t = lane & 3;
    const int m0   = blockIdx.y * 128;
    const int n0   = blockIdx.x * 128;

    float acc[2][8][4];
#pragma unroll
    for (int mf = 0; mf < 2; ++mf)
#pragma unroll
        for (int nf = 0; nf < 8; ++nf)
#pragma unroll
            for (int e = 0; e < 4; ++e) acc[mf][nf][e] = 0.0f;

    // per-thread cp.async geometry (same for all three tiles)
    const int crow = tid >> 2;          // j adds 64
    const int c16  = tid & 3;
    auto load_slab = [&](int ks, int st) {
        uint32_t base = smb + st * STAGE;
#pragma unroll
        for (int j = 0; j < 2; ++j) {
            int row = crow + j * 64;
            uint32_t d = base + row * PITCH + c16 * 16;
            cp_async16(d,          A  + (size_t)(m0 + row) * 1024 + ks * BKS + c16 * 8);
            cp_async16(d + OFF_BH, Bh + (size_t)(n0 + row) * 1024 + ks * BKS + c16 * 8);
            cp_async16(d + OFF_BL, Bl + (size_t)(n0 + row) * 1024 + ks * BKS + c16 * 8);
        }
        CP_COMMIT();
    };

    // ldmatrix lane addressing
    const int quad = lane >> 3, r8 = lane & 7;
    // A: quad0:(m r8,kh0) quad1:(m 8+r8,kh0) quad2:(m r8,kh1) quad3:(m 8+r8,kh1)
    const uint32_t aoff = (uint32_t)((wm * 32 + (quad & 1) * 8 + r8) * PITCH + (quad >> 1) * 16);
    // B: quad0:(n r8,kh0) quad1:(n r8,kh1) quad2:(n 8+r8,kh0) quad3:(n 8+r8,kh1)
    const uint32_t boff = (uint32_t)((wn * 64 + (quad >> 1) * 8 + r8) * PITCH + (quad & 1) * 16);

    // prologue: stages 0..2
    load_slab(0, 0);
    load_slab(1, 1);
    load_slab(2, 2);

#pragma unroll 1
    for (int i = 0; i < NSLAB; ++i) {
        cp_wait<2>();
        __syncthreads();
        const uint32_t st = smb + (uint32_t)(i & 3) * STAGE;
#pragma unroll
        for (int kk = 0; kk < 2; ++kk) {
            uint32_t a[2][4];
            ldm_x4(a[0], st + aoff + kk * 32);
            ldm_x4(a[1], st + aoff + kk * 32 + 16 * PITCH);
#pragma unroll
            for (int half = 0; half < 2; ++half) {
                const uint32_t bb = st + (half ? OFF_BL : OFF_BH) + boff + kk * 32;
#pragma unroll
                for (int nf2 = 0; nf2 < 4; ++nf2) {
                    uint32_t b[4];
                    ldm_x4(b, bb + nf2 * (16 * PITCH));
                    mma_f16(acc[0][2*nf2],   a[0], b);
                    mma_f16(acc[0][2*nf2+1], a[0], b + 2);
                    mma_f16(acc[1][2*nf2],   a[1], b);
                    mma_f16(acc[1][2*nf2+1], a[1], b + 2);
                }
            }
        }
        __syncthreads();
        if (i + 3 < NSLAB) load_slab(i + 3, (i + 3) & 3);
        else CP_COMMIT();
    }

    // Epilogue: bias add + store
#pragma unroll
    for (int mf = 0; mf < 2; ++mf) {
        int row = m0 + wm * 32 + mf * 16 + g;
#pragma unroll
        for (int nf = 0; nf < 8; ++nf) {
            int col = n0 + wn * 64 + nf * 8 + 2 * t;
            float b0 = bias[col], b1 = bias[col + 1];
            float2 o0 = make_float2(acc[mf][nf][0] + b0, acc[mf][nf][1] + b1);
            float2 o1 = make_float2(acc[mf][nf][2] + b0, acc[mf][nf][3] + b1);
            *(float2*)(C + (size_t)row * N + col)       = o0;
            *(float2*)(C + (size_t)(row + 8) * N + col) = o1;
        }
    }
}

// ---------------------------------------------------------------------------
// K2: per-token rmsnorm(q), rmsnorm(k), RoPE, ReLU — in place in g_qkv.
// ---------------------------------------------------------------------------
__global__ __launch_bounds__(256) void qk_prep_k(const float* __restrict__ gq,
                                                 const float* __restrict__ gk)
{
    const int t = blockIdx.x;
    const int l = t & (Lq - 1);
    const int tid = threadIdx.x;
    float* row = g_qkv + (size_t)t * NQKV;
    float4 q = *(float4*)(row + tid * 4);
    float4 k = *(float4*)(row + Dq + tid * 4);
    float sq = q.x*q.x + q.y*q.y + q.z*q.z + q.w*q.w;
    float sk = k.x*k.x + k.y*k.y + k.z*k.z + k.w*k.w;
#pragma unroll
    for (int o = 16; o > 0; o >>= 1) {
        sq += __shfl_xor_sync(0xffffffffu, sq, o);
        sk += __shfl_xor_sync(0xffffffffu, sk, o);
    }
    __shared__ float wq[8], wk[8];
    __shared__ float bq, bk;
    const int warp = tid >> 5, lane = tid & 31;
    if (lane == 0) { wq[warp] = sq; wk[warp] = sk; }
    __syncthreads();
    if (tid == 0) {
        float aq = 0.0f, ak = 0.0f;
#pragma unroll
        for (int i = 0; i < 8; ++i) { aq += wq[i]; ak += wk[i]; }
        bq = rsqrtf(aq * (1.0f / 1024.0f) + RMSEPS);
        bk = rsqrtf(ak * (1.0f / 1024.0f) + RMSEPS);
    }
    __syncthreads();
    const float scq = bq, sck = bk;
    const int c0 = tid * 4;
    float qe[4] = {q.x, q.y, q.z, q.w};
    float ke[4] = {k.x, k.y, k.z, k.w};
#pragma unroll
    for (int i = 0; i < 4; ++i) {
        qe[i] *= scq * gq[c0 + i];
        ke[i] *= sck * gk[c0 + i];
    }
#pragma unroll
    for (int p = 0; p < 2; ++p) {
        int d = (c0 + 2 * p) & 63;
        int j = d >> 1;
        float c = g_cos[l * 32 + j];
        float s = g_sin[l * 32 + j];
        float q0 = qe[2*p], q1 = qe[2*p + 1];
        qe[2*p]     = q0 * c - q1 * s;
        qe[2*p + 1] = q0 * s + q1 * c;
        float k0 = ke[2*p], k1 = ke[2*p + 1];
        ke[2*p]     = k0 * c - k1 * s;
        ke[2*p + 1] = k0 * s + k1 * c;
    }
    float4 qo = make_float4(fmaxf(qe[0],0.f), fmaxf(qe[1],0.f), fmaxf(qe[2],0.f), fmaxf(qe[3],0.f));
    float4 ko = make_float4(fmaxf(ke[0],0.f), fmaxf(ke[1],0.f), fmaxf(ke[2],0.f), fmaxf(ke[3],0.f));
    *(float4*)(row + tid * 4)      = qo;
    *(float4*)(row + Dq + tid * 4) = ko;
}

// ---------------------------------------------------------------------------
// K3: vk partials. CTA = (b*H+h, Lchunk of 256 tokens).
// ---------------------------------------------------------------------------
__global__ __launch_bounds__(256) void vk_accum_k() {
    const int bh = blockIdx.x;
    const int chunk = blockIdx.y;
    const int b = bh >> 4, h = bh & 15;
    const int tid = threadIdx.x;
    __shared__ __align__(16) float kf_s[32 * 64];
    __shared__ __align__(16) float vp_s[32 * 65];
    float acc[17];
#pragma unroll
    for (int i = 0; i < 17; ++i) acc[i] = 0.0f;
    if (tid < 32) vp_s[tid * 65 + 64] = 1.0f;
    const int tok0 = b * Lq + chunk * 256;
    const int r0 = tid >> 4;
    const int c4 = (tid & 15) << 2;
    for (int sub = 0; sub < 8; ++sub) {
        const int tbase = tok0 + sub * 32;
#pragma unroll
        for (int half = 0; half < 2; ++half) {
            int r = r0 + half * 16;
            const float* src = g_qkv + (size_t)(tbase + r) * NQKV + h * DHq + c4;
            float4 kv = *(const float4*)(src + Dq);
            float4 vv = *(const float4*)(src + 2 * Dq);
            *(float4*)&kf_s[r * 64 + c4] = kv;
            vp_s[r * 65 + c4 + 0] = vv.x;
            vp_s[r * 65 + c4 + 1] = vv.y;
            vp_s[r * 65 + c4 + 2] = vv.z;
            vp_s[r * 65 + c4 + 3] = vv.w;
        }
        __syncthreads();
#pragma unroll
        for (int ei = 0; ei < 17; ++ei) {
            const int e = tid + ei * 256;
            if (e < 65 * 64) {
                const int p = e >> 6, dd = e & 63;
                float a = acc[ei];
#pragma unroll
                for (int r = 0; r < 32; ++r)
                    a = fmaf(vp_s[r * 65 + p], kf_s[r * 64 + dd], a);
                acc[ei] = a;
            }
        }
        __syncthreads();
    }
#pragma unroll
    for (int ei = 0; ei < 17; ++ei) {
        const int e = tid + ei * 256;
        if (e < 65 * 64)
            g_vkp[(size_t)chunk * (64 * 65 * 64) + bh * (65 * 64) + e] = acc[ei];
    }
}

// K4: deterministic reduce of the 16 L-chunk partials.
__global__ void vk_reduce_k() {
    int i = blockIdx.x * 256 + threadIdx.x;
    if (i >= 64 * 65 * 64) return;
    float s = 0.0f;
#pragma unroll
    for (int c = 0; c < 16; ++c) s += g_vkp[(size_t)c * (64 * 65 * 64) + i];
    g_vk[i] = s;
}

// ---------------------------------------------------------------------------
// K5: res = vk . qf ; attn = res[:64]/(res[64]+eps)
// ---------------------------------------------------------------------------
__global__ __launch_bounds__(256) void attn_apply_k() {
    const int bh = blockIdx.x;
    const int lt = blockIdx.y;
    const int b = bh >> 4, h = bh & 15;
    const int tid = threadIdx.x;
    __shared__ __align__(16) float qf_s[64 * 64];
    __shared__ __align__(16) float vk_s[65 * 65];
#pragma unroll
    for (int ei = 0; ei < 17; ++ei) {
        int e = tid + ei * 256;
        if (e < 65 * 64) vk_s[(e >> 6) * 65 + (e & 63)] = g_vk[bh * (65 * 64) + e];
    }
    const int tok0 = b * Lq + lt * 64;
#pragma unroll
    for (int pass = 0; pass < 4; ++pass) {
        int fi = tid + pass * 256;
        int r = fi >> 4, c4 = (fi & 15) << 2;
        float4 v = *(const float4*)(g_qkv + (size_t)(tok0 + r) * NQKV + h * DHq + c4);
        *(float4*)&qf_s[r * 64 + c4] = v;
    }
    __syncthreads();
    const int dd = tid & 63;
    const int tsub = tid >> 6;
#pragma unroll 4
    for (int it = 0; it < 16; ++it) {
        const int tok = it * 4 + tsub;
        float num = 0.0f, den = 0.0f;
#pragma unroll
        for (int k = 0; k < 64; ++k) {
            float qv = qf_s[tok * 64 + k];
            num = fmaf(vk_s[dd * 65 + k], qv, num);
            den = fmaf(vk_s[64 * 65 + k], qv, den);
        }
        float o = num / (den + EPSLIN);
        const int lpos = lt * 64 + tok;
        g_attn[(size_t)(b * Lq + lpos) * Dq + h * DHq + dd] = o;
    }
}

// ---------------------------------------------------------------------------
// K7: final rmsnorm over g_y rows -> d_out
// ---------------------------------------------------------------------------
__global__ __launch_bounds__(256) void out_rms_k(const float* __restrict__ gout,
                                                 float* __restrict__ out)
{
    const int t = blockIdx.x;
    const int tid = threadIdx.x;
    const float* row = g_y + (size_t)t * Dq;
    float4 y = *(const float4*)(row + tid * 4);
    float ss = y.x*y.x + y.y*y.y + y.z*y.z + y.w*y.w;
#pragma unroll
    for (int o = 16; o > 0; o >>= 1) ss += __shfl_xor_sync(0xffffffffu, ss, o);
    __shared__ float w[8];
    __shared__ float bsc;
    if ((tid & 31) == 0) w[tid >> 5] = ss;
    __syncthreads();
    if (tid == 0) {
        float a = 0.0f;
#pragma unroll
        for (int i = 0; i < 8; ++i) a += w[i];
        bsc = rsqrtf(a * (1.0f / 1024.0f) + RMSEPS);
    }
    __syncthreads();
    const float sc = bsc;
    const int c0 = tid * 4;
    float4 o4;
    o4.x = y.x * sc * gout[c0 + 0];
    o4.y = y.y * sc * gout[c0 + 1];
    o4.z = y.z * sc * gout[c0 + 2];
    o4.w = y.w * sc * gout[c0 + 3];
    *(float4*)(out + (size_t)t * Dq + c0) = o4;
}

// ---------------------------------------------------------------------------
extern "C" void kernel_launch(void* const* d_in, const int* in_sizes, int n_in,
                              void* d_out, int out_size) {
    (void)in_sizes; (void)n_in; (void)out_size;
    const float* x    = (const float*)d_in[0];
    const float* Wqkv = (const float*)d_in[1];
    const float* bqkv = (const float*)d_in[2];
    const float* gq   = (const float*)d_in[3];
    const float* gk   = (const float*)d_in[4];
    const float* Wout = (const float*)d_in[5];
    const float* bout = (const float*)d_in[6];
    const float* gout = (const float*)d_in[7];
    float* out = (float*)d_out;

    float *qkv_p, *attn_p, *y_p;
    __half *xh, *ah, *wh1, *wl1, *wh2, *wl2;
    cudaGetSymbolAddress((void**)&qkv_p,  g_qkv);
    cudaGetSymbolAddress((void**)&attn_p, g_attn);
    cudaGetSymbolAddress((void**)&y_p,    g_y);
    cudaGetSymbolAddress((void**)&xh,  g_xh);
    cudaGetSymbolAddress((void**)&ah,  g_ah);
    cudaGetSymbolAddress((void**)&wh1, g_wh1);
    cudaGetSymbolAddress((void**)&wl1, g_wl1);
    cudaGetSymbolAddress((void**)&wh2, g_wh2);
    cudaGetSymbolAddress((void**)&wl2, g_wl2);

    const int DSMEM = NSTG * STAGE;   // 122880
    cudaFuncSetAttribute(gemm_hmma2_k, cudaFuncAttributeMaxDynamicSharedMemorySize, DSMEM);

    rope_tables_k<<<(Lq * 32 + 255) / 256, 256>>>();                          // 0
    to_half_k<<<(MTOK * Dq / 4 + 255) / 256, 256>>>(x, xh, MTOK * Dq / 4);    // 1
    split_half_k<<<(NQKV * Dq / 4 + 255) / 256, 256>>>(Wqkv, wh1, wl1, NQKV * Dq / 4); // 2
    gemm_hmma2_k<<<dim3(NQKV / 128, MTOK / 128), 256, DSMEM>>>(               // 3 (profiled slot)
        xh, wh1, wl1, bqkv, qkv_p, NQKV);
    split_half_k<<<(Dq * Dq / 4 + 255) / 256, 256>>>(Wout, wh2, wl2, Dq * Dq / 4);     // 4
    qk_prep_k<<<MTOK, 256>>>(gq, gk);
    vk_accum_k<<<dim3(64, 16), 256>>>();
    vk_reduce_k<<<(64 * 65 * 64 + 255) / 256, 256>>>();
    attn_apply_k<<<dim3(64, 64), 256>>>();
    to_half_k<<<(MTOK * Dq / 4 + 255) / 256, 256>>>(attn_p, ah, MTOK * Dq / 4);
    gemm_hmma2_k<<<dim3(Dq / 128, MTOK / 128), 256, DSMEM>>>(
        ah, wh2, wl2, bout, y_p, Dq);
    out_rms_k<<<MTOK, 256>>>(gout, out);
}

// round 6
// speedup vs baseline: 3.9512x; 1.4950x over previous
#include <cuda_runtime.h>
#include <cuda_fp16.h>
#include <math.h>
#include <stdint.h>

// Problem constants
#define Bq    4
#define Lq    4096
#define Dq    1024
#define Hq    16
#define DHq   64
#define MTOK  (Bq*Lq)      // 16384
#define NQKV  (3*Dq)       // 3072
#define RMSEPS 1.1920929e-07f
#define EPSLIN 1e-06f

// Scratch (device globals — no allocation allowed)
__device__ __align__(256) float g_qkv [(size_t)MTOK * NQKV];
__device__ __align__(256) float g_vkp [16 * 64 * 65 * DHq];
__device__ __align__(256) float g_vk  [64 * 65 * DHq];
__device__ __align__(256) float g_attn[(size_t)MTOK * Dq];
__device__ __align__(256) float g_y   [(size_t)MTOK * Dq];
__device__ __align__(256) float g_cos [Lq * 32];
__device__ __align__(256) float g_sin [Lq * 32];
// fp16 operands
__device__ __align__(256) __half g_xh [(size_t)MTOK * Dq];
__device__ __align__(256) __half g_ah [(size_t)MTOK * Dq];
__device__ __align__(256) __half g_wh1[(size_t)NQKV * Dq];
__device__ __align__(256) __half g_wh2[(size_t)Dq * Dq];

// ---------------------------------------------------------------------------
__device__ __forceinline__ uint32_t smem_u32(const void* p) {
    uint32_t a;
    asm("{ .reg .u64 t; cvta.to.shared.u64 t, %1; cvt.u32.u64 %0, t; }" : "=r"(a) : "l"(p));
    return a;
}
__device__ __forceinline__ void cp_async16(uint32_t dst, const void* src) {
    asm volatile("cp.async.cg.shared.global [%0], [%1], 16;" :: "r"(dst), "l"(src));
}
#define CP_COMMIT() asm volatile("cp.async.commit_group;" ::: "memory")
template <int N>
__device__ __forceinline__ void cp_wait() {
    asm volatile("cp.async.wait_group %0;" :: "n"(N) : "memory");
}
__device__ __forceinline__ void ldm_x4(uint32_t* r, uint32_t addr) {
    asm volatile("ldmatrix.sync.aligned.m8n8.x4.shared.b16 {%0,%1,%2,%3}, [%4];"
                 : "=r"(r[0]), "=r"(r[1]), "=r"(r[2]), "=r"(r[3]) : "r"(addr));
}
__device__ __forceinline__ void mma_f16(float* c, const uint32_t* a, const uint32_t* b) {
    asm volatile(
        "mma.sync.aligned.m16n8k16.row.col.f32.f16.f16.f32 "
        "{%0,%1,%2,%3}, {%4,%5,%6,%7}, {%8,%9}, {%0,%1,%2,%3};"
        : "+f"(c[0]), "+f"(c[1]), "+f"(c[2]), "+f"(c[3])
        : "r"(a[0]), "r"(a[1]), "r"(a[2]), "r"(a[3]), "r"(b[0]), "r"(b[1]));
}

// ---------------------------------------------------------------------------
// K0: RoPE tables
// ---------------------------------------------------------------------------
__global__ void rope_tables_k() {
    int idx = blockIdx.x * blockDim.x + threadIdx.x;
    if (idx >= Lq * 32) return;
    int l = idx >> 5, j = idx & 31;
    float inv_freq = expf(-(float)j * (9.210340371976184f / 32.0f));
    float ang = (float)l * inv_freq;
    g_cos[idx] = cosf(ang);
    g_sin[idx] = sinf(ang);
}

// fp32 -> fp16
__global__ __launch_bounds__(256) void to_half_k(
    const float* __restrict__ s, __half* __restrict__ d, int n4)
{
    int i = blockIdx.x * 256 + threadIdx.x;
    if (i >= n4) return;
    float4 v = ((const float4*)s)[i];
    __half2 h0 = __floats2half2_rn(v.x, v.y);
    __half2 h1 = __floats2half2_rn(v.z, v.w);
    ((__half2*)d)[2*i]   = h0;
    ((__half2*)d)[2*i+1] = h1;
}

// ---------------------------------------------------------------------------
// HMMA GEMM v3: C[m,n] = sum_k A[m,k]*B[n,k] + bias[n], K = 1024.
// Single fp16 pass. Tile 128x128, 256 thr (8 warps = 4m x 2n, warp 32x64).
// cp.async 4-stage pipeline; ldmatrix.x4; pitch 80B; 2 CTAs/SM.
// ---------------------------------------------------------------------------
#define BKS     32
#define NSLAB   32                  // 1024/32
#define PITCH   80                  // bytes per row (64B data + 16B pad)
#define TILEB   (128 * PITCH)       // 10240
#define OFF_B   TILEB
#define STAGE   (2 * TILEB)         // 20480
#define NSTG    4

__global__ __launch_bounds__(256, 2)
void gemm_hmma3_k(const __half* __restrict__ A, const __half* __restrict__ B,
                  const float* __restrict__ bias, float* __restrict__ C, int N)
{
    extern __shared__ __align__(16) char sm[];
    const uint32_t smb = smem_u32(sm);
    const int tid  = threadIdx.x;
    const int wid  = tid >> 5, lane = tid & 31;
    const int wm   = wid & 3, wn = wid >> 2;
    const int g    = lane >> 2, t = lane & 3;
    const int m0   = blockIdx.y * 128;
    const int n0   = blockIdx.x * 128;

    float acc[2][8][4];
#pragma unroll
    for (int mf = 0; mf < 2; ++mf)
#pragma unroll
        for (int nf = 0; nf < 8; ++nf)
#pragma unroll
            for (int e = 0; e < 4; ++e) acc[mf][nf][e] = 0.0f;

    const int crow = tid >> 2;
    const int c16  = tid & 3;
    auto load_slab = [&](int ks, int st) {
        uint32_t base = smb + st * STAGE;
#pragma unroll
        for (int j = 0; j < 2; ++j) {
            int row = crow + j * 64;
            uint32_t d = base + row * PITCH + c16 * 16;
            cp_async16(d,         A + (size_t)(m0 + row) * 1024 + ks * BKS + c16 * 8);
            cp_async16(d + OFF_B, B + (size_t)(n0 + row) * 1024 + ks * BKS + c16 * 8);
        }
        CP_COMMIT();
    };

    const int quad = lane >> 3, r8 = lane & 7;
    const uint32_t aoff = (uint32_t)((wm * 32 + (quad & 1) * 8 + r8) * PITCH + (quad >> 1) * 16);
    const uint32_t boff = (uint32_t)((wn * 64 + (quad >> 1) * 8 + r8) * PITCH + (quad & 1) * 16);

    load_slab(0, 0);
    load_slab(1, 1);
    load_slab(2, 2);

#pragma unroll 1
    for (int i = 0; i < NSLAB; ++i) {
        cp_wait<2>();
        __syncthreads();
        const uint32_t st = smb + (uint32_t)(i & 3) * STAGE;
#pragma unroll
        for (int kk = 0; kk < 2; ++kk) {
            uint32_t a[2][4];
            ldm_x4(a[0], st + aoff + kk * 32);
            ldm_x4(a[1], st + aoff + kk * 32 + 16 * PITCH);
            const uint32_t bb = st + OFF_B + boff + kk * 32;
#pragma unroll
            for (int nf2 = 0; nf2 < 4; ++nf2) {
                uint32_t b[4];
                ldm_x4(b, bb + nf2 * (16 * PITCH));
                mma_f16(acc[0][2*nf2],   a[0], b);
                mma_f16(acc[0][2*nf2+1], a[0], b + 2);
                mma_f16(acc[1][2*nf2],   a[1], b);
                mma_f16(acc[1][2*nf2+1], a[1], b + 2);
            }
        }
        __syncthreads();
        if (i + 3 < NSLAB) load_slab(i + 3, (i + 3) & 3);
        else CP_COMMIT();
    }

#pragma unroll
    for (int mf = 0; mf < 2; ++mf) {
        int row = m0 + wm * 32 + mf * 16 + g;
#pragma unroll
        for (int nf = 0; nf < 8; ++nf) {
            int col = n0 + wn * 64 + nf * 8 + 2 * t;
            float b0 = bias[col], b1 = bias[col + 1];
            float2 o0 = make_float2(acc[mf][nf][0] + b0, acc[mf][nf][1] + b1);
            float2 o1 = make_float2(acc[mf][nf][2] + b0, acc[mf][nf][3] + b1);
            *(float2*)(C + (size_t)row * N + col)       = o0;
            *(float2*)(C + (size_t)(row + 8) * N + col) = o1;
        }
    }
}

// ---------------------------------------------------------------------------
// K2: per-token rmsnorm(q), rmsnorm(k), RoPE, ReLU — in place in g_qkv.
// ---------------------------------------------------------------------------
__global__ __launch_bounds__(256) void qk_prep_k(const float* __restrict__ gq,
                                                 const float* __restrict__ gk)
{
    const int t = blockIdx.x;
    const int l = t & (Lq - 1);
    const int tid = threadIdx.x;
    float* row = g_qkv + (size_t)t * NQKV;
    float4 q = *(float4*)(row + tid * 4);
    float4 k = *(float4*)(row + Dq + tid * 4);
    float sq = q.x*q.x + q.y*q.y + q.z*q.z + q.w*q.w;
    float sk = k.x*k.x + k.y*k.y + k.z*k.z + k.w*k.w;
#pragma unroll
    for (int o = 16; o > 0; o >>= 1) {
        sq += __shfl_xor_sync(0xffffffffu, sq, o);
        sk += __shfl_xor_sync(0xffffffffu, sk, o);
    }
    __shared__ float wq[8], wk[8];
    __shared__ float bq, bk;
    const int warp = tid >> 5, lane = tid & 31;
    if (lane == 0) { wq[warp] = sq; wk[warp] = sk; }
    __syncthreads();
    if (tid == 0) {
        float aq = 0.0f, ak = 0.0f;
#pragma unroll
        for (int i = 0; i < 8; ++i) { aq += wq[i]; ak += wk[i]; }
        bq = rsqrtf(aq * (1.0f / 1024.0f) + RMSEPS);
        bk = rsqrtf(ak * (1.0f / 1024.0f) + RMSEPS);
    }
    __syncthreads();
    const float scq = bq, sck = bk;
    const int c0 = tid * 4;
    float qe[4] = {q.x, q.y, q.z, q.w};
    float ke[4] = {k.x, k.y, k.z, k.w};
#pragma unroll
    for (int i = 0; i < 4; ++i) {
        qe[i] *= scq * gq[c0 + i];
        ke[i] *= sck * gk[c0 + i];
    }
#pragma unroll
    for (int p = 0; p < 2; ++p) {
        int d = (c0 + 2 * p) & 63;
        int j = d >> 1;
        float c = g_cos[l * 32 + j];
        float s = g_sin[l * 32 + j];
        float q0 = qe[2*p], q1 = qe[2*p + 1];
        qe[2*p]     = q0 * c - q1 * s;
        qe[2*p + 1] = q0 * s + q1 * c;
        float k0 = ke[2*p], k1 = ke[2*p + 1];
        ke[2*p]     = k0 * c - k1 * s;
        ke[2*p + 1] = k0 * s + k1 * c;
    }
    float4 qo = make_float4(fmaxf(qe[0],0.f), fmaxf(qe[1],0.f), fmaxf(qe[2],0.f), fmaxf(qe[3],0.f));
    float4 ko = make_float4(fmaxf(ke[0],0.f), fmaxf(ke[1],0.f), fmaxf(ke[2],0.f), fmaxf(ke[3],0.f));
    *(float4*)(row + tid * 4)      = qo;
    *(float4*)(row + Dq + tid * 4) = ko;
}

// ---------------------------------------------------------------------------
// K3: vk partials. CTA = (b*H+h, Lchunk of 256 tokens).
// ---------------------------------------------------------------------------
__global__ __launch_bounds__(256) void vk_accum_k() {
    const int bh = blockIdx.x;
    const int chunk = blockIdx.y;
    const int b = bh >> 4, h = bh & 15;
    const int tid = threadIdx.x;
    __shared__ __align__(16) float kf_s[32 * 64];
    __shared__ __align__(16) float vp_s[32 * 65];
    float acc[17];
#pragma unroll
    for (int i = 0; i < 17; ++i) acc[i] = 0.0f;
    if (tid < 32) vp_s[tid * 65 + 64] = 1.0f;
    const int tok0 = b * Lq + chunk * 256;
    const int r0 = tid >> 4;
    const int c4 = (tid & 15) << 2;
    for (int sub = 0; sub < 8; ++sub) {
        const int tbase = tok0 + sub * 32;
#pragma unroll
        for (int half = 0; half < 2; ++half) {
            int r = r0 + half * 16;
            const float* src = g_qkv + (size_t)(tbase + r) * NQKV + h * DHq + c4;
            float4 kv = *(const float4*)(src + Dq);
            float4 vv = *(const float4*)(src + 2 * Dq);
            *(float4*)&kf_s[r * 64 + c4] = kv;
            vp_s[r * 65 + c4 + 0] = vv.x;
            vp_s[r * 65 + c4 + 1] = vv.y;
            vp_s[r * 65 + c4 + 2] = vv.z;
            vp_s[r * 65 + c4 + 3] = vv.w;
        }
        __syncthreads();
#pragma unroll
        for (int ei = 0; ei < 17; ++ei) {
            const int e = tid + ei * 256;
            if (e < 65 * 64) {
                const int p = e >> 6, dd = e & 63;
                float a = acc[ei];
#pragma unroll
                for (int r = 0; r < 32; ++r)
                    a = fmaf(vp_s[r * 65 + p], kf_s[r * 64 + dd], a);
                acc[ei] = a;
            }
        }
        __syncthreads();
    }
#pragma unroll
    for (int ei = 0; ei < 17; ++ei) {
        const int e = tid + ei * 256;
        if (e < 65 * 64)
            g_vkp[(size_t)chunk * (64 * 65 * 64) + bh * (65 * 64) + e] = acc[ei];
    }
}

// K4: deterministic reduce of the 16 L-chunk partials.
__global__ void vk_reduce_k() {
    int i = blockIdx.x * 256 + threadIdx.x;
    if (i >= 64 * 65 * 64) return;
    float s = 0.0f;
#pragma unroll
    for (int c = 0; c < 16; ++c) s += g_vkp[(size_t)c * (64 * 65 * 64) + i];
    g_vk[i] = s;
}

// ---------------------------------------------------------------------------
// K5: res = vk . qf ; attn = res[:64]/(res[64]+eps)
// ---------------------------------------------------------------------------
__global__ __launch_bounds__(256) void attn_apply_k() {
    const int bh = blockIdx.x;
    const int lt = blockIdx.y;
    const int b = bh >> 4, h = bh & 15;
    const int tid = threadIdx.x;
    __shared__ __align__(16) float qf_s[64 * 64];
    __shared__ __align__(16) float vk_s[65 * 65];
#pragma unroll
    for (int ei = 0; ei < 17; ++ei) {
        int e = tid + ei * 256;
        if (e < 65 * 64) vk_s[(e >> 6) * 65 + (e & 63)] = g_vk[bh * (65 * 64) + e];
    }
    const int tok0 = b * Lq + lt * 64;
#pragma unroll
    for (int pass = 0; pass < 4; ++pass) {
        int fi = tid + pass * 256;
        int r = fi >> 4, c4 = (fi & 15) << 2;
        float4 v = *(const float4*)(g_qkv + (size_t)(tok0 + r) * NQKV + h * DHq + c4);
        *(float4*)&qf_s[r * 64 + c4] = v;
    }
    __syncthreads();
    const int dd = tid & 63;
    const int tsub = tid >> 6;
#pragma unroll 4
    for (int it = 0; it < 16; ++it) {
        const int tok = it * 4 + tsub;
        float num = 0.0f, den = 0.0f;
#pragma unroll
        for (int k = 0; k < 64; ++k) {
            float qv = qf_s[tok * 64 + k];
            num = fmaf(vk_s[dd * 65 + k], qv, num);
            den = fmaf(vk_s[64 * 65 + k], qv, den);
        }
        float o = num / (den + EPSLIN);
        const int lpos = lt * 64 + tok;
        g_attn[(size_t)(b * Lq + lpos) * Dq + h * DHq + dd] = o;
    }
}

// ---------------------------------------------------------------------------
// K7: final rmsnorm over g_y rows -> d_out
// ---------------------------------------------------------------------------
__global__ __launch_bounds__(256) void out_rms_k(const float* __restrict__ gout,
                                                 float* __restrict__ out)
{
    const int t = blockIdx.x;
    const int tid = threadIdx.x;
    const float* row = g_y + (size_t)t * Dq;
    float4 y = *(const float4*)(row + tid * 4);
    float ss = y.x*y.x + y.y*y.y + y.z*y.z + y.w*y.w;
#pragma unroll
    for (int o = 16; o > 0; o >>= 1) ss += __shfl_xor_sync(0xffffffffu, ss, o);
    __shared__ float w[8];
    __shared__ float bsc;
    if ((tid & 31) == 0) w[tid >> 5] = ss;
    __syncthreads();
    if (tid == 0) {
        float a = 0.0f;
#pragma unroll
        for (int i = 0; i < 8; ++i) a += w[i];
        bsc = rsqrtf(a * (1.0f / 1024.0f) + RMSEPS);
    }
    __syncthreads();
    const float sc = bsc;
    const int c0 = tid * 4;
    float4 o4;
    o4.x = y.x * sc * gout[c0 + 0];
    o4.y = y.y * sc * gout[c0 + 1];
    o4.z = y.z * sc * gout[c0 + 2];
    o4.w = y.w * sc * gout[c0 + 3];
    *(float4*)(out + (size_t)t * Dq + c0) = o4;
}

// ---------------------------------------------------------------------------
extern "C" void kernel_launch(void* const* d_in, const int* in_sizes, int n_in,
                              void* d_out, int out_size) {
    (void)in_sizes; (void)n_in; (void)out_size;
    const float* x    = (const float*)d_in[0];
    const float* Wqkv = (const float*)d_in[1];
    const float* bqkv = (const float*)d_in[2];
    const float* gq   = (const float*)d_in[3];
    const float* gk   = (const float*)d_in[4];
    const float* Wout = (const float*)d_in[5];
    const float* bout = (const float*)d_in[6];
    const float* gout = (const float*)d_in[7];
    float* out = (float*)d_out;

    float *qkv_p, *attn_p, *y_p;
    __half *xh, *ah, *wh1, *wh2;
    cudaGetSymbolAddress((void**)&qkv_p,  g_qkv);
    cudaGetSymbolAddress((void**)&attn_p, g_attn);
    cudaGetSymbolAddress((void**)&y_p,    g_y);
    cudaGetSymbolAddress((void**)&xh,  g_xh);
    cudaGetSymbolAddress((void**)&ah,  g_ah);
    cudaGetSymbolAddress((void**)&wh1, g_wh1);
    cudaGetSymbolAddress((void**)&wh2, g_wh2);

    const int DSMEM = NSTG * STAGE;   // 81920
    cudaFuncSetAttribute(gemm_hmma3_k, cudaFuncAttributeMaxDynamicSharedMemorySize, DSMEM);

    rope_tables_k<<<(Lq * 32 + 255) / 256, 256>>>();                          // 0
    to_half_k<<<(MTOK * Dq / 4 + 255) / 256, 256>>>(x, xh, MTOK * Dq / 4);    // 1
    to_half_k<<<(NQKV * Dq / 4 + 255) / 256, 256>>>(Wqkv, wh1, NQKV * Dq / 4);// 2
    gemm_hmma3_k<<<dim3(NQKV / 128, MTOK / 128), 256, DSMEM>>>(               // 3 (profiled slot)
        xh, wh1, bqkv, qkv_p, NQKV);
    to_half_k<<<(Dq * Dq / 4 + 255) / 256, 256>>>(Wout, wh2, Dq * Dq / 4);    // 4
    qk_prep_k<<<MTOK, 256>>>(gq, gk);
    vk_accum_k<<<dim3(64, 16), 256>>>();
    vk_reduce_k<<<(64 * 65 * 64 + 255) / 256, 256>>>();
    attn_apply_k<<<dim3(64, 64), 256>>>();
    to_half_k<<<(MTOK * Dq / 4 + 255) / 256, 256>>>(attn_p, ah, MTOK * Dq / 4);
    gemm_hmma3_k<<<dim3(Dq / 128, MTOK / 128), 256, DSMEM>>>(
        ah, wh2, bout, y_p, Dq);
    out_rms_k<<<MTOK, 256>>>(gout, out);
}

// round 7
// speedup vs baseline: 4.6326x; 1.1725x over previous
#include <cuda_runtime.h>
#include <cuda_fp16.h>
#include <math.h>
#include <stdint.h>

// Problem constants
#define Bq    4
#define Lq    4096
#define Dq    1024
#define Hq    16
#define DHq   64
#define MTOK  (Bq*Lq)      // 16384
#define NQKV  (3*Dq)       // 3072
#define RMSEPS 1.1920929e-07f
#define EPSLIN 1e-06f

// Scratch (device globals — no allocation allowed)
__device__ __align__(256) float g_qkv [(size_t)MTOK * NQKV];
__device__ __align__(256) float g_vkp [16 * 64 * 65 * DHq];
__device__ __align__(256) float g_vk  [64 * 65 * DHq];
__device__ __align__(256) float g_y   [(size_t)MTOK * Dq];
__device__ __align__(256) float g_cos [Lq * 32];
__device__ __align__(256) float g_sin [Lq * 32];
// fp16 operands
__device__ __align__(256) __half g_xh [(size_t)MTOK * Dq];
__device__ __align__(256) __half g_ah [(size_t)MTOK * Dq];   // attn in fp16 (gemm2 A)
__device__ __align__(256) __half g_wh1[(size_t)NQKV * Dq];
__device__ __align__(256) __half g_wh2[(size_t)Dq * Dq];

// ---------------------------------------------------------------------------
__device__ __forceinline__ uint32_t smem_u32(const void* p) {
    uint32_t a;
    asm("{ .reg .u64 t; cvta.to.shared.u64 t, %1; cvt.u32.u64 %0, t; }" : "=r"(a) : "l"(p));
    return a;
}
__device__ __forceinline__ void cp_async16(uint32_t dst, const void* src) {
    asm volatile("cp.async.cg.shared.global [%0], [%1], 16;" :: "r"(dst), "l"(src));
}
#define CP_COMMIT() asm volatile("cp.async.commit_group;" ::: "memory")
template <int N>
__device__ __forceinline__ void cp_wait() {
    asm volatile("cp.async.wait_group %0;" :: "n"(N) : "memory");
}
__device__ __forceinline__ void ldm_x4(uint32_t* r, uint32_t addr) {
    asm volatile("ldmatrix.sync.aligned.m8n8.x4.shared.b16 {%0,%1,%2,%3}, [%4];"
                 : "=r"(r[0]), "=r"(r[1]), "=r"(r[2]), "=r"(r[3]) : "r"(addr));
}
__device__ __forceinline__ void mma_f16(float* c, const uint32_t* a, const uint32_t* b) {
    asm volatile(
        "mma.sync.aligned.m16n8k16.row.col.f32.f16.f16.f32 "
        "{%0,%1,%2,%3}, {%4,%5,%6,%7}, {%8,%9}, {%0,%1,%2,%3};"
        : "+f"(c[0]), "+f"(c[1]), "+f"(c[2]), "+f"(c[3])
        : "r"(a[0]), "r"(a[1]), "r"(a[2]), "r"(a[3]), "r"(b[0]), "r"(b[1]));
}

// ---------------------------------------------------------------------------
// K0: RoPE tables
// ---------------------------------------------------------------------------
__global__ void rope_tables_k() {
    int idx = blockIdx.x * blockDim.x + threadIdx.x;
    if (idx >= Lq * 32) return;
    int l = idx >> 5, j = idx & 31;
    float inv_freq = expf(-(float)j * (9.210340371976184f / 32.0f));
    float ang = (float)l * inv_freq;
    g_cos[idx] = cosf(ang);
    g_sin[idx] = sinf(ang);
}

// fp32 -> fp16
__global__ __launch_bounds__(256) void to_half_k(
    const float* __restrict__ s, __half* __restrict__ d, int n4)
{
    int i = blockIdx.x * 256 + threadIdx.x;
    if (i >= n4) return;
    float4 v = ((const float4*)s)[i];
    __half2 h0 = __floats2half2_rn(v.x, v.y);
    __half2 h1 = __floats2half2_rn(v.z, v.w);
    ((__half2*)d)[2*i]   = h0;
    ((__half2*)d)[2*i+1] = h1;
}

// ---------------------------------------------------------------------------
// HMMA GEMM v4: C[m,n] = sum_k A[m,k]*B[n,k] + bias[n], K = 1024.
// Single fp16 pass. Tile 128x128, 256 thr (8 warps = 4m x 2n, warp 32x64).
// cp.async 4-stage pipeline with load issue BEFORE compute; single barrier/slab.
// ---------------------------------------------------------------------------
#define BKS     32
#define NSLAB   32                  // 1024/32
#define PITCH   80                  // bytes per row (64B data + 16B pad)
#define TILEB   (128 * PITCH)       // 10240
#define OFF_B   TILEB
#define STAGE   (2 * TILEB)         // 20480
#define NSTG    4

__global__ __launch_bounds__(256, 2)
void gemm_hmma3_k(const __half* __restrict__ A, const __half* __restrict__ B,
                  const float* __restrict__ bias, float* __restrict__ C, int N)
{
    extern __shared__ __align__(16) char sm[];
    const uint32_t smb = smem_u32(sm);
    const int tid  = threadIdx.x;
    const int wid  = tid >> 5, lane = tid & 31;
    const int wm   = wid & 3, wn = wid >> 2;
    const int g    = lane >> 2, t = lane & 3;
    const int m0   = blockIdx.y * 128;
    const int n0   = blockIdx.x * 128;

    float acc[2][8][4];
#pragma unroll
    for (int mf = 0; mf < 2; ++mf)
#pragma unroll
        for (int nf = 0; nf < 8; ++nf)
#pragma unroll
            for (int e = 0; e < 4; ++e) acc[mf][nf][e] = 0.0f;

    const int crow = tid >> 2;
    const int c16  = tid & 3;
    auto load_slab = [&](int ks, int st) {
        uint32_t base = smb + st * STAGE;
#pragma unroll
        for (int j = 0; j < 2; ++j) {
            int row = crow + j * 64;
            uint32_t d = base + row * PITCH + c16 * 16;
            cp_async16(d,         A + (size_t)(m0 + row) * 1024 + ks * BKS + c16 * 8);
            cp_async16(d + OFF_B, B + (size_t)(n0 + row) * 1024 + ks * BKS + c16 * 8);
        }
        CP_COMMIT();
    };

    const int quad = lane >> 3, r8 = lane & 7;
    const uint32_t aoff = (uint32_t)((wm * 32 + (quad & 1) * 8 + r8) * PITCH + (quad >> 1) * 16);
    const uint32_t boff = (uint32_t)((wn * 64 + (quad >> 1) * 8 + r8) * PITCH + (quad & 1) * 16);

    load_slab(0, 0);
    load_slab(1, 1);
    load_slab(2, 2);

#pragma unroll 1
    for (int i = 0; i < NSLAB; ++i) {
        cp_wait<2>();
        __syncthreads();
        // Safe to overwrite stage (i+3)&3 == (i-1)&3: consumed in iter i-1 and
        // all threads passed the barrier above (which follows their iter i-1 compute).
        if (i + 3 < NSLAB) load_slab(i + 3, (i + 3) & 3);
        else CP_COMMIT();                 // keep group count aligned for cp_wait<2>
        const uint32_t st = smb + (uint32_t)(i & 3) * STAGE;
#pragma unroll
        for (int kk = 0; kk < 2; ++kk) {
            uint32_t a[2][4];
            ldm_x4(a[0], st + aoff + kk * 32);
            ldm_x4(a[1], st + aoff + kk * 32 + 16 * PITCH);
            const uint32_t bb = st + OFF_B + boff + kk * 32;
#pragma unroll
            for (int nf2 = 0; nf2 < 4; ++nf2) {
                uint32_t b[4];
                ldm_x4(b, bb + nf2 * (16 * PITCH));
                mma_f16(acc[0][2*nf2],   a[0], b);
                mma_f16(acc[0][2*nf2+1], a[0], b + 2);
                mma_f16(acc[1][2*nf2],   a[1], b);
                mma_f16(acc[1][2*nf2+1], a[1], b + 2);
            }
        }
    }

#pragma unroll
    for (int mf = 0; mf < 2; ++mf) {
        int row = m0 + wm * 32 + mf * 16 + g;
#pragma unroll
        for (int nf = 0; nf < 8; ++nf) {
            int col = n0 + wn * 64 + nf * 8 + 2 * t;
            float b0 = bias[col], b1 = bias[col + 1];
            float2 o0 = make_float2(acc[mf][nf][0] + b0, acc[mf][nf][1] + b1);
            float2 o1 = make_float2(acc[mf][nf][2] + b0, acc[mf][nf][3] + b1);
            *(float2*)(C + (size_t)row * N + col)       = o0;
            *(float2*)(C + (size_t)(row + 8) * N + col) = o1;
        }
    }
}

// ---------------------------------------------------------------------------
// K2: per-token rmsnorm(q), rmsnorm(k), RoPE, ReLU — in place in g_qkv.
// ---------------------------------------------------------------------------
__global__ __launch_bounds__(256) void qk_prep_k(const float* __restrict__ gq,
                                                 const float* __restrict__ gk)
{
    const int t = blockIdx.x;
    const int l = t & (Lq - 1);
    const int tid = threadIdx.x;
    float* row = g_qkv + (size_t)t * NQKV;
    float4 q = *(float4*)(row + tid * 4);
    float4 k = *(float4*)(row + Dq + tid * 4);
    float sq = q.x*q.x + q.y*q.y + q.z*q.z + q.w*q.w;
    float sk = k.x*k.x + k.y*k.y + k.z*k.z + k.w*k.w;
#pragma unroll
    for (int o = 16; o > 0; o >>= 1) {
        sq += __shfl_xor_sync(0xffffffffu, sq, o);
        sk += __shfl_xor_sync(0xffffffffu, sk, o);
    }
    __shared__ float wq[8], wk[8];
    __shared__ float bq, bk;
    const int warp = tid >> 5, lane = tid & 31;
    if (lane == 0) { wq[warp] = sq; wk[warp] = sk; }
    __syncthreads();
    if (tid == 0) {
        float aq = 0.0f, ak = 0.0f;
#pragma unroll
        for (int i = 0; i < 8; ++i) { aq += wq[i]; ak += wk[i]; }
        bq = rsqrtf(aq * (1.0f / 1024.0f) + RMSEPS);
        bk = rsqrtf(ak * (1.0f / 1024.0f) + RMSEPS);
    }
    __syncthreads();
    const float scq = bq, sck = bk;
    const int c0 = tid * 4;
    float qe[4] = {q.x, q.y, q.z, q.w};
    float ke[4] = {k.x, k.y, k.z, k.w};
#pragma unroll
    for (int i = 0; i < 4; ++i) {
        qe[i] *= scq * gq[c0 + i];
        ke[i] *= sck * gk[c0 + i];
    }
#pragma unroll
    for (int p = 0; p < 2; ++p) {
        int d = (c0 + 2 * p) & 63;
        int j = d >> 1;
        float c = g_cos[l * 32 + j];
        float s = g_sin[l * 32 + j];
        float q0 = qe[2*p], q1 = qe[2*p + 1];
        qe[2*p]     = q0 * c - q1 * s;
        qe[2*p + 1] = q0 * s + q1 * c;
        float k0 = ke[2*p], k1 = ke[2*p + 1];
        ke[2*p]     = k0 * c - k1 * s;
        ke[2*p + 1] = k0 * s + k1 * c;
    }
    float4 qo = make_float4(fmaxf(qe[0],0.f), fmaxf(qe[1],0.f), fmaxf(qe[2],0.f), fmaxf(qe[3],0.f));
    float4 ko = make_float4(fmaxf(ke[0],0.f), fmaxf(ke[1],0.f), fmaxf(ke[2],0.f), fmaxf(ke[3],0.f));
    *(float4*)(row + tid * 4)      = qo;
    *(float4*)(row + Dq + tid * 4) = ko;
}

// ---------------------------------------------------------------------------
// K3: vk partials, register-tiled. CTA = (b*H+h, Lchunk of 256 tokens).
// Thread (pq,dq) owns 4x4 (p,d) outputs; den (p=64 row) folded into pq==0.
// ---------------------------------------------------------------------------
__global__ __launch_bounds__(256) void vk_accum_k() {
    const int bh = blockIdx.x;
    const int chunk = blockIdx.y;
    const int b = bh >> 4, h = bh & 15;
    const int tid = threadIdx.x;
    __shared__ __align__(16) float kf_s[32 * 64];
    __shared__ __align__(16) float vp_s[32 * 64];
    const int pq = tid >> 4;           // 0..15 -> p base pq*4
    const int dq = tid & 15;           // 0..15 -> d base dq*4
    float acc[4][4];
    float den[4] = {0.f, 0.f, 0.f, 0.f};
#pragma unroll
    for (int i = 0; i < 4; ++i)
#pragma unroll
        for (int j = 0; j < 4; ++j) acc[i][j] = 0.0f;

    const int tok0 = b * Lq + chunk * 256;
    const int r0 = tid >> 4;
    const int c4 = (tid & 15) << 2;
    for (int sub = 0; sub < 8; ++sub) {
        const int tbase = tok0 + sub * 32;
#pragma unroll
        for (int half = 0; half < 2; ++half) {
            int r = r0 + half * 16;
            const float* src = g_qkv + (size_t)(tbase + r) * NQKV + h * DHq + c4;
            *(float4*)&kf_s[r * 64 + c4] = *(const float4*)(src + Dq);
            *(float4*)&vp_s[r * 64 + c4] = *(const float4*)(src + 2 * Dq);
        }
        __syncthreads();
#pragma unroll 8
        for (int r = 0; r < 32; ++r) {
            float4 vp = *(const float4*)&vp_s[r * 64 + pq * 4];
            float4 kf = *(const float4*)&kf_s[r * 64 + dq * 4];
            const float kfe[4] = {kf.x, kf.y, kf.z, kf.w};
            const float vpe[4] = {vp.x, vp.y, vp.z, vp.w};
#pragma unroll
            for (int i = 0; i < 4; ++i)
#pragma unroll
                for (int j = 0; j < 4; ++j)
                    acc[i][j] = fmaf(vpe[i], kfe[j], acc[i][j]);
            if (pq == 0) {
#pragma unroll
                for (int j = 0; j < 4; ++j) den[j] += kfe[j];
            }
        }
        __syncthreads();
    }
    float* dst = g_vkp + (size_t)chunk * (64 * 65 * 64) + bh * (65 * 64);
#pragma unroll
    for (int i = 0; i < 4; ++i) {
        float4 o = make_float4(acc[i][0], acc[i][1], acc[i][2], acc[i][3]);
        *(float4*)(dst + (pq * 4 + i) * 64 + dq * 4) = o;
    }
    if (pq == 0)
        *(float4*)(dst + 64 * 64 + dq * 4) = make_float4(den[0], den[1], den[2], den[3]);
}

// K4: deterministic reduce of the 16 L-chunk partials.
__global__ void vk_reduce_k() {
    int i = blockIdx.x * 256 + threadIdx.x;
    if (i >= 64 * 65 * 64) return;
    float s = 0.0f;
#pragma unroll
    for (int c = 0; c < 16; ++c) s += g_vkp[(size_t)c * (64 * 65 * 64) + i];
    g_vk[i] = s;
}

// ---------------------------------------------------------------------------
// K5: res = vk . qf ; attn = res[:64]/(res[64]+eps) -> fp16 into g_ah
// ---------------------------------------------------------------------------
__global__ __launch_bounds__(256) void attn_apply_k() {
    const int bh = blockIdx.x;
    const int lt = blockIdx.y;
    const int b = bh >> 4, h = bh & 15;
    const int tid = threadIdx.x;
    __shared__ __align__(16) float qf_s[64 * 64];
    __shared__ __align__(16) float vk_s[65 * 65];
#pragma unroll
    for (int ei = 0; ei < 17; ++ei) {
        int e = tid + ei * 256;
        if (e < 65 * 64) vk_s[(e >> 6) * 65 + (e & 63)] = g_vk[bh * (65 * 64) + e];
    }
    const int tok0 = b * Lq + lt * 64;
#pragma unroll
    for (int pass = 0; pass < 4; ++pass) {
        int fi = tid + pass * 256;
        int r = fi >> 4, c4 = (fi & 15) << 2;
        float4 v = *(const float4*)(g_qkv + (size_t)(tok0 + r) * NQKV + h * DHq + c4);
        *(float4*)&qf_s[r * 64 + c4] = v;
    }
    __syncthreads();
    const int dd = tid & 63;
    const int tsub = tid >> 6;
#pragma unroll 4
    for (int it = 0; it < 16; ++it) {
        const int tok = it * 4 + tsub;
        float num = 0.0f, den = 0.0f;
#pragma unroll
        for (int k = 0; k < 64; ++k) {
            float qv = qf_s[tok * 64 + k];
            num = fmaf(vk_s[dd * 65 + k], qv, num);
            den = fmaf(vk_s[64 * 65 + k], qv, den);
        }
        float o = num / (den + EPSLIN);
        const int lpos = lt * 64 + tok;
        g_ah[(size_t)(b * Lq + lpos) * Dq + h * DHq + dd] = __float2half_rn(o);
    }
}

// ---------------------------------------------------------------------------
// K7: final rmsnorm over g_y rows -> d_out
// ---------------------------------------------------------------------------
__global__ __launch_bounds__(256) void out_rms_k(const float* __restrict__ gout,
                                                 float* __restrict__ out)
{
    const int t = blockIdx.x;
    const int tid = threadIdx.x;
    const float* row = g_y + (size_t)t * Dq;
    float4 y = *(const float4*)(row + tid * 4);
    float ss = y.x*y.x + y.y*y.y + y.z*y.z + y.w*y.w;
#pragma unroll
    for (int o = 16; o > 0; o >>= 1) ss += __shfl_xor_sync(0xffffffffu, ss, o);
    __shared__ float w[8];
    __shared__ float bsc;
    if ((tid & 31) == 0) w[tid >> 5] = ss;
    __syncthreads();
    if (tid == 0) {
        float a = 0.0f;
#pragma unroll
        for (int i = 0; i < 8; ++i) a += w[i];
        bsc = rsqrtf(a * (1.0f / 1024.0f) + RMSEPS);
    }
    __syncthreads();
    const float sc = bsc;
    const int c0 = tid * 4;
    float4 o4;
    o4.x = y.x * sc * gout[c0 + 0];
    o4.y = y.y * sc * gout[c0 + 1];
    o4.z = y.z * sc * gout[c0 + 2];
    o4.w = y.w * sc * gout[c0 + 3];
    *(float4*)(out + (size_t)t * Dq + c0) = o4;
}

// ---------------------------------------------------------------------------
extern "C" void kernel_launch(void* const* d_in, const int* in_sizes, int n_in,
                              void* d_out, int out_size) {
    (void)in_sizes; (void)n_in; (void)out_size;
    const float* x    = (const float*)d_in[0];
    const float* Wqkv = (const float*)d_in[1];
    const float* bqkv = (const float*)d_in[2];
    const float* gq   = (const float*)d_in[3];
    const float* gk   = (const float*)d_in[4];
    const float* Wout = (const float*)d_in[5];
    const float* bout = (const float*)d_in[6];
    const float* gout = (const float*)d_in[7];
    float* out = (float*)d_out;

    float *qkv_p, *y_p;
    __half *xh, *ah, *wh1, *wh2;
    cudaGetSymbolAddress((void**)&qkv_p, g_qkv);
    cudaGetSymbolAddress((void**)&y_p,   g_y);
    cudaGetSymbolAddress((void**)&xh,  g_xh);
    cudaGetSymbolAddress((void**)&ah,  g_ah);
    cudaGetSymbolAddress((void**)&wh1, g_wh1);
    cudaGetSymbolAddress((void**)&wh2, g_wh2);

    const int DSMEM = NSTG * STAGE;   // 81920
    cudaFuncSetAttribute(gemm_hmma3_k, cudaFuncAttributeMaxDynamicSharedMemorySize, DSMEM);

    rope_tables_k<<<(Lq * 32 + 255) / 256, 256>>>();                          // 0
    to_half_k<<<(MTOK * Dq / 4 + 255) / 256, 256>>>(x, xh, MTOK * Dq / 4);    // 1
    to_half_k<<<(NQKV * Dq / 4 + 255) / 256, 256>>>(Wqkv, wh1, NQKV * Dq / 4);// 2
    gemm_hmma3_k<<<dim3(NQKV / 128, MTOK / 128), 256, DSMEM>>>(               // 3 (profiled slot)
        xh, wh1, bqkv, qkv_p, NQKV);
    to_half_k<<<(Dq * Dq / 4 + 255) / 256, 256>>>(Wout, wh2, Dq * Dq / 4);    // 4
    qk_prep_k<<<MTOK, 256>>>(gq, gk);
    vk_accum_k<<<dim3(64, 16), 256>>>();
    vk_reduce_k<<<(64 * 65 * 64 + 255) / 256, 256>>>();
    attn_apply_k<<<dim3(64, 64), 256>>>();
    gemm_hmma3_k<<<dim3(Dq / 128, MTOK / 128), 256, DSMEM>>>(
        ah, wh2, bout, y_p, Dq);
    out_rms_k<<<MTOK, 256>>>(gout, out);
}